// round 4
// baseline (speedup 1.0000x reference)
#include <cuda_runtime.h>
#include <cuda_bf16.h>
#include <cstdint>

// ---------------------------------------------------------------------------
// CrossBundleAttention — HMMA (mma.sync bf16 hi/lo) for KV-proj + lift,
// fp32 split-K for small GEMMs, fused batched attention, LayerNorm.
// B=64, M=2048, D_LLM=4096, bundles: (d=256,nh=4,s=4) (512,8,8) (1024,16,4)
// ---------------------------------------------------------------------------

#define BATCH 64
#define MEM   2048
#define DLLM  4096

// ======================= scratch (device globals) ==========================
__device__ float g_qb[BATCH * 1024];
__device__ float g_qp[BATCH * 1024];
__device__ float g_o [BATCH * 1024];
__device__ float g_o2[BATCH * 1024];
__device__ float g_part[8 * BATCH * 1024];
__device__ float g_kv[2 * MEM * 1024];               // K then V
__device__ float g_prefix[BATCH * 16 * DLLM];
__device__ __nv_bfloat16 g_fh[MEM * 1024],  g_fl[MEM * 1024];
__device__ __nv_bfloat16 g_wkvh[2 * 1024 * 1024], g_wkvl[2 * 1024 * 1024];
__device__ __nv_bfloat16 g_wlh[16777216], g_wll[16777216];   // transposed Wlift
__device__ __nv_bfloat16 g_o2h[128 * 1024], g_o2l[128 * 1024];

// ======================= conversion kernels ================================
__global__ void cvt_hilo(const float* __restrict__ src,
                         __nv_bfloat16* __restrict__ hi, __nv_bfloat16* __restrict__ lo, int n) {
    int i = blockIdx.x * 256 + threadIdx.x;
    if (i >= n) return;
    float x = src[i];
    __nv_bfloat16 h = __float2bfloat16(x);
    hi[i] = h;
    lo[i] = __float2bfloat16(x - __bfloat162float(h));
}

__global__ void cvt_hilo_pad(const float* __restrict__ src,
                             __nv_bfloat16* __restrict__ hi, __nv_bfloat16* __restrict__ lo,
                             int rows_valid, int Kd) {
    int i = blockIdx.x * 256 + threadIdx.x;
    if (i >= 128 * Kd) return;
    int r = i / Kd;
    if (r < rows_valid) {
        float x = src[i];
        __nv_bfloat16 h = __float2bfloat16(x);
        hi[i] = h;
        lo[i] = __float2bfloat16(x - __bfloat162float(h));
    } else {
        hi[i] = __float2bfloat16(0.f);
        lo[i] = __float2bfloat16(0.f);
    }
}

// Wlift (s, K, 4096) -> transposed hi/lo (s, 4096, K)
__global__ void transp_hilo(const float* __restrict__ src,
                            __nv_bfloat16* __restrict__ hi, __nv_bfloat16* __restrict__ lo, int K) {
    __shared__ float t[32][33];
    const int s = blockIdx.z;
    const int n0 = blockIdx.x * 32, k0 = blockIdx.y * 32;
    const int tx = threadIdx.x, ty = threadIdx.y;
    const float* sp = src + (size_t)s * K * DLLM;
#pragma unroll
    for (int j = 0; j < 32; j += 8)
        t[ty + j][tx] = sp[(size_t)(k0 + ty + j) * DLLM + n0 + tx];
    __syncthreads();
    size_t dbase = (size_t)s * DLLM * K;
#pragma unroll
    for (int j = 0; j < 32; j += 8) {
        float x = t[tx][ty + j];
        __nv_bfloat16 h = __float2bfloat16(x);
        size_t di = dbase + (size_t)(n0 + ty + j) * K + k0 + tx;
        hi[di] = h;
        lo[di] = __float2bfloat16(x - __bfloat162float(h));
    }
}

// ======================= HMMA hi/lo GEMM-NT ================================
// C[z][m][n] = sum_k A[m][k]*B[z][n][k] + bias[z][n]  (fp32 out, bf16 hi/lo in)
// Block tile 128x128, 8 warps of 64x32, K-chunk 64.
#define STR 72   // smem row stride in bf16 (64 data + 8 pad) -> conflict-free frags

__device__ __forceinline__ void mma16816(float* c, const uint32_t* a, const uint32_t* b) {
    asm volatile(
        "mma.sync.aligned.m16n8k16.row.col.f32.bf16.bf16.f32 "
        "{%0,%1,%2,%3}, {%4,%5,%6,%7}, {%8,%9}, {%0,%1,%2,%3};"
        : "+f"(c[0]), "+f"(c[1]), "+f"(c[2]), "+f"(c[3])
        : "r"(a[0]), "r"(a[1]), "r"(a[2]), "r"(a[3]), "r"(b[0]), "r"(b[1]));
}

#define HMMA_SMEM (4 * 128 * STR * 2)   // Ah, Al, Bh, Bl tiles = 73728 B

__global__ void __launch_bounds__(256) hmma_nt(
    const __nv_bfloat16* __restrict__ a_hi, const __nv_bfloat16* __restrict__ a_lo,
    const __nv_bfloat16* __restrict__ b_hi, const __nv_bfloat16* __restrict__ b_lo,
    const float* __restrict__ bias, long long bias_zstr,
    float* __restrict__ C, long long c_row, long long c_zstr,
    long long b_zstr, int K, int m_valid)
{
    extern __shared__ __nv_bfloat16 sm[];
    __nv_bfloat16* Ah = sm;
    __nv_bfloat16* Al = sm + 128 * STR;
    __nv_bfloat16* Bh = sm + 2 * 128 * STR;
    __nv_bfloat16* Bl = sm + 3 * 128 * STR;

    const int tid = threadIdx.x, wid = tid >> 5, lane = tid & 31;
    const int nBase = blockIdx.x << 7, mBase = blockIdx.y << 7, z = blockIdx.z;
    const int mW = (wid >> 2) << 6;      // warp M offset in tile (0/64)
    const int nW = (wid & 3) << 5;       // warp N offset in tile (0/32/64/96)
    const __nv_bfloat16* bh = b_hi + (size_t)z * b_zstr;
    const __nv_bfloat16* bl = b_lo + (size_t)z * b_zstr;

    float acc[4][4][4] = {};
    const int grp = lane >> 2;           // 0..7
    const int qid = lane & 3;            // 0..3

    for (int k0 = 0; k0 < K; k0 += 64) {
        // ---- stage tiles: 128 rows x 64 bf16 each (uint4 = 8 bf16) ----
#pragma unroll
        for (int it = 0; it < 4; it++) {
            const int i = (it << 8) + tid;
            const int r = i >> 3, c8 = (i & 7) << 3;
            const size_t ga = (size_t)(mBase + r) * K + k0 + c8;
            const size_t gb = (size_t)(nBase + r) * K + k0 + c8;
            const int so = r * STR + c8;
            *(uint4*)(Ah + so) = *(const uint4*)(a_hi + ga);
            *(uint4*)(Al + so) = *(const uint4*)(a_lo + ga);
            *(uint4*)(Bh + so) = *(const uint4*)(bh + gb);
            *(uint4*)(Bl + so) = *(const uint4*)(bl + gb);
        }
        __syncthreads();

#pragma unroll
        for (int kk = 0; kk < 4; kk++) {
            const int kc = (kk << 4) + (qid << 1);
            uint32_t ah[4][4], al[4][4], bhf[4][2], blf[4][2];
#pragma unroll
            for (int mi = 0; mi < 4; mi++) {
                const int r = mW + (mi << 4) + grp;
                ah[mi][0] = *(const uint32_t*)(Ah + r * STR + kc);
                ah[mi][1] = *(const uint32_t*)(Ah + (r + 8) * STR + kc);
                ah[mi][2] = *(const uint32_t*)(Ah + r * STR + kc + 8);
                ah[mi][3] = *(const uint32_t*)(Ah + (r + 8) * STR + kc + 8);
                al[mi][0] = *(const uint32_t*)(Al + r * STR + kc);
                al[mi][1] = *(const uint32_t*)(Al + (r + 8) * STR + kc);
                al[mi][2] = *(const uint32_t*)(Al + r * STR + kc + 8);
                al[mi][3] = *(const uint32_t*)(Al + (r + 8) * STR + kc + 8);
            }
#pragma unroll
            for (int ni = 0; ni < 4; ni++) {
                const int n = nW + (ni << 3) + grp;
                bhf[ni][0] = *(const uint32_t*)(Bh + n * STR + kc);
                bhf[ni][1] = *(const uint32_t*)(Bh + n * STR + kc + 8);
                blf[ni][0] = *(const uint32_t*)(Bl + n * STR + kc);
                blf[ni][1] = *(const uint32_t*)(Bl + n * STR + kc + 8);
            }
#pragma unroll
            for (int mi = 0; mi < 4; mi++)
#pragma unroll
                for (int ni = 0; ni < 4; ni++) {
                    mma16816(acc[mi][ni], ah[mi], bhf[ni]);
                    mma16816(acc[mi][ni], ah[mi], blf[ni]);
                    mma16816(acc[mi][ni], al[mi], bhf[ni]);
                }
        }
        __syncthreads();
    }

    // ---- epilogue ----
    const float* brow = bias + (size_t)z * bias_zstr;
    float* Cz = C + (size_t)z * c_zstr;
#pragma unroll
    for (int mi = 0; mi < 4; mi++) {
        const int r0 = mBase + mW + (mi << 4) + grp;
#pragma unroll
        for (int ni = 0; ni < 4; ni++) {
            const int c = nBase + nW + (ni << 3) + (qid << 1);
            if (r0 < m_valid) {
                float2 v = {acc[mi][ni][0] + brow[c], acc[mi][ni][1] + brow[c + 1]};
                *(float2*)(Cz + (size_t)r0 * c_row + c) = v;
            }
            if (r0 + 8 < m_valid) {
                float2 v = {acc[mi][ni][2] + brow[c], acc[mi][ni][3] + brow[c + 1]};
                *(float2*)(Cz + (size_t)(r0 + 8) * c_row + c) = v;
            }
        }
    }
}

// ======================= fp32 split-K GEMM (M=64) ==========================
#define BN 64
#define BK 16
#define PAD 68
__global__ void __launch_bounds__(256) gemm_nt_splitk(
    const float* __restrict__ A, const float* __restrict__ W,
    float* __restrict__ Cpart, int N, int K)
{
    __shared__ float As[BK][PAD];
    __shared__ float Ws[BK][PAD];
    const int tid = threadIdx.x;
    const int tx = tid & 15, ty = tid >> 4;
    const int nBase = blockIdx.x * BN;
    const int z = blockIdx.z;
    const int kc = K >> 3;
    const int lr = tid >> 2;
    const int lc = (tid & 3) << 2;
    const float* Ap = A + (size_t)lr * K + lc;
    const float* Wp = W + (size_t)(nBase + lr) * K + lc;
    float acc[4][4] = {};
    const int kEnd = z * kc + kc;
    for (int k0 = z * kc; k0 < kEnd; k0 += BK) {
        float4 a4 = *(const float4*)(Ap + k0);
        float4 w4 = *(const float4*)(Wp + k0);
        As[lc + 0][lr] = a4.x; As[lc + 1][lr] = a4.y;
        As[lc + 2][lr] = a4.z; As[lc + 3][lr] = a4.w;
        Ws[lc + 0][lr] = w4.x; Ws[lc + 1][lr] = w4.y;
        Ws[lc + 2][lr] = w4.z; Ws[lc + 3][lr] = w4.w;
        __syncthreads();
#pragma unroll
        for (int kk = 0; kk < BK; kk++) {
            float4 av = *(const float4*)&As[kk][ty << 2];
            float4 wv = *(const float4*)&Ws[kk][tx << 2];
            float am[4] = {av.x, av.y, av.z, av.w};
            float wm[4] = {wv.x, wv.y, wv.z, wv.w};
#pragma unroll
            for (int i = 0; i < 4; i++)
#pragma unroll
                for (int j = 0; j < 4; j++)
                    acc[i][j] += am[i] * wm[j];
        }
        __syncthreads();
    }
    float* Cp = Cpart + (size_t)z * BATCH * N;
#pragma unroll
    for (int i = 0; i < 4; i++) {
        const int m = (ty << 2) + i;
#pragma unroll
        for (int j = 0; j < 4; j++) {
            const int n = nBase + (tx << 2) + j;
            Cp[(size_t)m * N + n] = acc[i][j];
        }
    }
}

__global__ void reduce8(const float* __restrict__ part, const float* __restrict__ bias,
                        float* __restrict__ C, int MN, int N, float alpha)
{
    const int i = blockIdx.x * 256 + threadIdx.x;
    if (i >= MN) return;
    float s = bias[i % N];
#pragma unroll
    for (int z = 0; z < 8; z++) s += part[(size_t)z * MN + i];
    C[i] = alpha * s;
}

// ======================= batched-query attention ===========================
// grid (nh, B/8), block 256. 8 queries per block share K/V tile reads.
// dyn smem: qs[8*64] | sc[8*2048] | ts[64*65]  = 21056 floats
__global__ void __launch_bounds__(256) attn2(
    const float* __restrict__ qp, const float* __restrict__ Kp,
    const float* __restrict__ Vp, const unsigned char* __restrict__ mask,
    float* __restrict__ o, int d)
{
    extern __shared__ float smf[];
    float* qs = smf;                 // 512
    float* sc = smf + 512;           // 16384
    float* ts = smf + 512 + 16384;   // 64*65

    const int h = blockIdx.x, b0 = blockIdx.y << 3;
    const int base = h << 6;
    const int tid = threadIdx.x, lane = tid & 31, wid = tid >> 5;

    for (int i = tid; i < 512; i += 256) {
        int qq = i >> 6, k = i & 63;
        qs[i] = qp[(size_t)(b0 + qq) * d + base + k];
    }
    __syncthreads();

    const float4* qs4 = (const float4*)(qs + (wid << 6));
    const unsigned char* mrow = mask + (size_t)(b0 + wid) * MEM;

    // phase 1: scores
    for (int mc = 0; mc < MEM; mc += 64) {
        for (int i = tid; i < 64 * 64; i += 256) {
            int r = i >> 6, c = i & 63;
            ts[r * 65 + c] = Kp[(size_t)(mc + r) * d + base + c];
        }
        __syncthreads();
        float acc0 = 0.f, acc1 = 0.f;
        const float* t0 = ts + lane * 65;
        const float* t1 = ts + (lane + 32) * 65;
#pragma unroll
        for (int k4 = 0; k4 < 16; k4++) {
            float4 qv = qs4[k4];
            acc0 += qv.x * t0[k4 * 4] + qv.y * t0[k4 * 4 + 1] + qv.z * t0[k4 * 4 + 2] + qv.w * t0[k4 * 4 + 3];
            acc1 += qv.x * t1[k4 * 4] + qv.y * t1[k4 * 4 + 1] + qv.z * t1[k4 * 4 + 2] + qv.w * t1[k4 * 4 + 3];
        }
        sc[(wid << 11) + mc + lane]      = mrow[mc + lane]      ? -1e9f : acc0;
        sc[(wid << 11) + mc + 32 + lane] = mrow[mc + 32 + lane] ? -1e9f : acc1;
        __syncthreads();
    }

    // warp-local softmax (warp w owns query b0+w)
    float* row = sc + (wid << 11);
    float mx = -1e30f;
    for (int i = lane; i < MEM; i += 32) mx = fmaxf(mx, row[i]);
#pragma unroll
    for (int off = 16; off; off >>= 1) mx = fmaxf(mx, __shfl_xor_sync(0xffffffffu, mx, off));
    float sum = 0.f;
    for (int i = lane; i < MEM; i += 32) {
        float e = __expf(row[i] - mx);
        row[i] = e;
        sum += e;
    }
#pragma unroll
    for (int off = 16; off; off >>= 1) sum += __shfl_xor_sync(0xffffffffu, sum, off);
    const float inv = 1.f / sum;

    // phase 2: P @ V
    float acc0 = 0.f, acc1 = 0.f;
    for (int mc = 0; mc < MEM; mc += 64) {
        __syncthreads();
        for (int i = tid; i < 64 * 64; i += 256) {
            int r = i >> 6, c = i & 63;
            ts[r * 65 + c] = Vp[(size_t)(mc + r) * d + base + c];
        }
        __syncthreads();
        const float* pr = row + mc;
#pragma unroll 8
        for (int j = 0; j < 64; j++) {
            float p = pr[j];
            acc0 += p * ts[j * 65 + lane];
            acc1 += p * ts[j * 65 + lane + 32];
        }
    }
    o[(size_t)(b0 + wid) * d + base + lane]      = acc0 * inv;
    o[(size_t)(b0 + wid) * d + base + lane + 32] = acc1 * inv;
}

// ======================= LayerNorm =========================================
__global__ void __launch_bounds__(256) ln_kernel(
    const float* __restrict__ x, const float* __restrict__ g,
    const float* __restrict__ be, float* __restrict__ out)
{
    __shared__ float rs[8], rss[8];
    __shared__ float s_mu, s_inv;
    const int rowi = blockIdx.x;
    const float4* xr = (const float4*)(x + (size_t)rowi * DLLM);
    const int tid = threadIdx.x, lane = tid & 31, warp = tid >> 5;
    float s = 0.f, ss = 0.f;
    for (int i = tid; i < DLLM / 4; i += 256) {
        float4 v = xr[i];
        s  += v.x + v.y + v.z + v.w;
        ss += v.x * v.x + v.y * v.y + v.z * v.z + v.w * v.w;
    }
#pragma unroll
    for (int off = 16; off; off >>= 1) {
        s  += __shfl_xor_sync(0xffffffffu, s, off);
        ss += __shfl_xor_sync(0xffffffffu, ss, off);
    }
    if (lane == 0) { rs[warp] = s; rss[warp] = ss; }
    __syncthreads();
    if (tid == 0) {
        float S = 0.f, SS = 0.f;
#pragma unroll
        for (int w = 0; w < 8; w++) { S += rs[w]; SS += rss[w]; }
        const float mu = S * (1.0f / DLLM);
        const float var = SS * (1.0f / DLLM) - mu * mu;
        s_mu = mu;
        s_inv = rsqrtf(var + 1e-5f);
    }
    __syncthreads();
    const float mu = s_mu, inv = s_inv;
    const float4* g4 = (const float4*)g;
    const float4* b4 = (const float4*)be;
    float4* outr = (float4*)(out + (size_t)rowi * DLLM);
    for (int i = tid; i < DLLM / 4; i += 256) {
        float4 v = xr[i], gv = g4[i], bv = b4[i];
        float4 r;
        r.x = (v.x - mu) * inv * gv.x + bv.x;
        r.y = (v.y - mu) * inv * gv.y + bv.y;
        r.z = (v.z - mu) * inv * gv.z + bv.z;
        r.w = (v.w - mu) * inv * gv.w + bv.w;
        outr[i] = r;
    }
}

// ======================= host orchestration ================================
extern "C" void kernel_launch(void* const* d_in, const int* in_sizes, int n_in,
                              void* d_out, int out_size)
{
    const float* hidden = (const float*)d_in[0];
    const float* fibers[3] = {(const float*)d_in[1], (const float*)d_in[2], (const float*)d_in[3]};
    const unsigned char* mask = (const unsigned char*)d_in[4];
    const float* Wq[3]    = {(const float*)d_in[5],  (const float*)d_in[7],  (const float*)d_in[9]};
    const float* bq[3]    = {(const float*)d_in[6],  (const float*)d_in[8],  (const float*)d_in[10]};
    const float* Wqkv[3]  = {(const float*)d_in[11], (const float*)d_in[15], (const float*)d_in[19]};
    const float* bqkv[3]  = {(const float*)d_in[12], (const float*)d_in[16], (const float*)d_in[20]};
    const float* Wo[3]    = {(const float*)d_in[13], (const float*)d_in[17], (const float*)d_in[21]};
    const float* bo[3]    = {(const float*)d_in[14], (const float*)d_in[18], (const float*)d_in[22]};
    const float* Wlift[3] = {(const float*)d_in[23], (const float*)d_in[25], (const float*)d_in[27]};
    const float* blift[3] = {(const float*)d_in[24], (const float*)d_in[26], (const float*)d_in[28]};
    const float* lng = (const float*)d_in[29];
    const float* lnb = (const float*)d_in[30];

    const int ds[3]       = {256, 512, 1024};
    const int nhs[3]      = {4, 8, 16};
    const int slots[3]    = {4, 8, 4};
    const int slotBase[3] = {0, 4, 12};

    float *qb, *qp, *oo, *o2, *part, *kv, *prefix;
    __nv_bfloat16 *fh, *fl, *wkvh, *wkvl, *wlh, *wll, *o2h, *o2l;
    cudaGetSymbolAddress((void**)&qb, g_qb);
    cudaGetSymbolAddress((void**)&qp, g_qp);
    cudaGetSymbolAddress((void**)&oo, g_o);
    cudaGetSymbolAddress((void**)&o2, g_o2);
    cudaGetSymbolAddress((void**)&part, g_part);
    cudaGetSymbolAddress((void**)&kv, g_kv);
    cudaGetSymbolAddress((void**)&prefix, g_prefix);
    cudaGetSymbolAddress((void**)&fh, g_fh);
    cudaGetSymbolAddress((void**)&fl, g_fl);
    cudaGetSymbolAddress((void**)&wkvh, g_wkvh);
    cudaGetSymbolAddress((void**)&wkvl, g_wkvl);
    cudaGetSymbolAddress((void**)&wlh, g_wlh);
    cudaGetSymbolAddress((void**)&wll, g_wll);
    cudaGetSymbolAddress((void**)&o2h, g_o2h);
    cudaGetSymbolAddress((void**)&o2l, g_o2l);

    cudaFuncSetAttribute(hmma_nt, cudaFuncAttributeMaxDynamicSharedMemorySize, HMMA_SMEM);
    cudaFuncSetAttribute(attn2, cudaFuncAttributeMaxDynamicSharedMemorySize, 21056 * 4);

    for (int bi = 0; bi < 3; bi++) {
        const int d = ds[bi], nh = nhs[bi], s = slots[bi];
        const int MN = BATCH * d;
        const int rblocks = (MN + 255) / 256;

        // --- conversions ---
        cvt_hilo<<<(MEM * d + 255) / 256, 256>>>(fibers[bi], fh, fl, MEM * d);
        cvt_hilo<<<(2 * d * d + 255) / 256, 256>>>(Wqkv[bi] + (size_t)d * d, wkvh, wkvl, 2 * d * d);
        transp_hilo<<<dim3(DLLM / 32, d / 32, s), dim3(32, 8)>>>(Wlift[bi], wlh, wll, d);

        // --- q head + q in-proj (fp32 split-K) ---
        gemm_nt_splitk<<<dim3(d / 64, 1, 8), 256>>>(hidden, Wq[bi], part, d, DLLM);
        reduce8<<<rblocks, 256>>>(part, bq[bi], qb, MN, d, 1.0f);
        gemm_nt_splitk<<<dim3(d / 64, 1, 8), 256>>>(qb, Wqkv[bi], part, d, d);
        reduce8<<<rblocks, 256>>>(part, bqkv[bi], qp, MN, d, 0.125f);

        // --- K and V projections (HMMA hi/lo) ---
        hmma_nt<<<dim3(d / 128, MEM / 128, 2), 256, HMMA_SMEM>>>(
            fh, fl, wkvh, wkvl, bqkv[bi] + d, d,
            kv, d, (long long)MEM * d, (long long)d * d, d, MEM);

        // --- attention ---
        attn2<<<dim3(nh, BATCH / 8), 256, 21056 * 4>>>(
            qp, kv, kv + (size_t)MEM * d, mask, oo, d);

        // --- out-proj (fp32 split-K) ---
        gemm_nt_splitk<<<dim3(d / 64, 1, 8), 256>>>(oo, Wo[bi], part, d, d);
        reduce8<<<rblocks, 256>>>(part, bo[bi], o2, MN, d, 1.0f);

        // --- lift (HMMA hi/lo, M padded to 128) ---
        cvt_hilo_pad<<<(128 * d + 255) / 256, 256>>>(o2, o2h, o2l, BATCH, d);
        hmma_nt<<<dim3(DLLM / 128, 1, s), 256, HMMA_SMEM>>>(
            o2h, o2l, wlh, wll, blift[bi], DLLM,
            prefix + (size_t)slotBase[bi] * DLLM, 16 * DLLM, DLLM,
            (long long)DLLM * d, d, BATCH);
    }

    ln_kernel<<<BATCH * 16, 256>>>(prefix, lng, lnb, (float*)d_out);
}

// round 5
// speedup vs baseline: 1.8116x; 1.8116x over previous
#include <cuda_runtime.h>
#include <cuda_bf16.h>
#include <cstdint>

// ---------------------------------------------------------------------------
// CrossBundleAttention — multi-stream fork/join + ldmatrix HMMA hi/lo GEMMs
// B=64, M=2048, D_LLM=4096, bundles: (d=256,nh=4,s=4) (512,8,8) (1024,16,4)
// ---------------------------------------------------------------------------

#define BATCH 64
#define MEM   2048
#define DLLM  4096
#define STR   72      // smem row stride (bf16): 64 data + 8 pad

// ======================= scratch (device globals) ==========================
__device__ float g_prefix[4194304];
__device__ float g_kvf[7340032];                 // per-bundle K|V fp32
__device__ float g_qb[114688], g_qp[114688], g_o[114688], g_o2[114688];
__device__ float g_qpart[3670016];               // q-head split-K partials
__device__ float g_skpart[917504];               // small split-K partials
__device__ __nv_bfloat16 g_hidh[524288], g_hidl[524288];     // hidden padded to 128 rows
__device__ __nv_bfloat16 g_fh[3670016],  g_fl[3670016];      // fibers
__device__ __nv_bfloat16 g_wqh[7340032], g_wql[7340032];     // Wq (3 bundles)
__device__ __nv_bfloat16 g_wkvh[2752512], g_wkvl[2752512];   // Wk|Wv
__device__ __nv_bfloat16 g_wlh[37748736], g_wll[37748736];   // Wlift transposed
__device__ __nv_bfloat16 g_o2h[229376], g_o2l[229376];       // o2 padded

// ======================= conversion kernels ================================
__global__ void cvt_hilo(const float* __restrict__ src,
                         __nv_bfloat16* __restrict__ hi, __nv_bfloat16* __restrict__ lo, int n) {
    int i = blockIdx.x * 256 + threadIdx.x;
    if (i >= n) return;
    float x = src[i];
    __nv_bfloat16 h = __float2bfloat16(x);
    hi[i] = h;
    lo[i] = __float2bfloat16(x - __bfloat162float(h));
}

__global__ void cvt_hilo_pad(const float* __restrict__ src,
                             __nv_bfloat16* __restrict__ hi, __nv_bfloat16* __restrict__ lo,
                             int rows_valid, int Kd) {
    int i = blockIdx.x * 256 + threadIdx.x;
    if (i >= 128 * Kd) return;
    int r = i / Kd;
    if (r < rows_valid) {
        float x = src[i];
        __nv_bfloat16 h = __float2bfloat16(x);
        hi[i] = h;
        lo[i] = __float2bfloat16(x - __bfloat162float(h));
    } else {
        hi[i] = __float2bfloat16(0.f);
        lo[i] = __float2bfloat16(0.f);
    }
}

// Wlift (s, K, 4096) -> transposed hi/lo (s, 4096, K)
__global__ void transp_hilo(const float* __restrict__ src,
                            __nv_bfloat16* __restrict__ hi, __nv_bfloat16* __restrict__ lo, int K) {
    __shared__ float t[32][33];
    const int s = blockIdx.z;
    const int n0 = blockIdx.x * 32, k0 = blockIdx.y * 32;
    const int tx = threadIdx.x, ty = threadIdx.y;
    const float* sp = src + (size_t)s * K * DLLM;
#pragma unroll
    for (int j = 0; j < 32; j += 8)
        t[ty + j][tx] = sp[(size_t)(k0 + ty + j) * DLLM + n0 + tx];
    __syncthreads();
    size_t dbase = (size_t)s * DLLM * K;
#pragma unroll
    for (int j = 0; j < 32; j += 8) {
        float x = t[tx][ty + j];
        __nv_bfloat16 h = __float2bfloat16(x);
        size_t di = dbase + (size_t)(n0 + ty + j) * K + k0 + tx;
        hi[di] = h;
        lo[di] = __float2bfloat16(x - __bfloat162float(h));
    }
}

// ======================= HMMA hi/lo GEMM-NT ================================
__device__ __forceinline__ void mma16816(float* c, const uint32_t* a, const uint32_t* b) {
    asm volatile(
        "mma.sync.aligned.m16n8k16.row.col.f32.bf16.bf16.f32 "
        "{%0,%1,%2,%3}, {%4,%5,%6,%7}, {%8,%9}, {%0,%1,%2,%3};"
        : "+f"(c[0]), "+f"(c[1]), "+f"(c[2]), "+f"(c[3])
        : "r"(a[0]), "r"(a[1]), "r"(a[2]), "r"(a[3]), "r"(b[0]), "r"(b[1]));
}
__device__ __forceinline__ void ldm4(uint32_t* r, const __nv_bfloat16* p) {
    uint32_t a = (uint32_t)__cvta_generic_to_shared(p);
    asm volatile("ldmatrix.sync.aligned.m8n8.x4.shared.b16 {%0,%1,%2,%3}, [%4];"
        : "=r"(r[0]), "=r"(r[1]), "=r"(r[2]), "=r"(r[3]) : "r"(a));
}

#define HMMA_SMEM ((2 * 128 * STR + 2 * 64 * STR) * 2)   // 55296 B

// Block tile 128x64, 8 warps (4x2), warp tile 32x32.
// Full mode (kslice==0): C[z][m][n] = sum_k A[m][k]*B[z][n][k] + bias[z][n]
// Partial mode (kslice>0): z = K-slice index; Cpart[z][m][n] partial, no bias.
__global__ void __launch_bounds__(256) hmma_k(
    const __nv_bfloat16* __restrict__ a_hi, const __nv_bfloat16* __restrict__ a_lo,
    const __nv_bfloat16* __restrict__ b_hi, const __nv_bfloat16* __restrict__ b_lo,
    const float* __restrict__ bias, long long bias_zstr,
    float* __restrict__ C, long long c_row, long long c_zstr,
    long long b_zstr, int K, int m_valid, int kslice)
{
    extern __shared__ __nv_bfloat16 sm[];
    __nv_bfloat16* Ah = sm;
    __nv_bfloat16* Al = sm + 128 * STR;
    __nv_bfloat16* Bh = sm + 2 * 128 * STR;
    __nv_bfloat16* Bl = Bh + 64 * STR;

    const int tid = threadIdx.x, wid = tid >> 5, lane = tid & 31;
    const int nBase = blockIdx.x << 6, mBase = blockIdx.y << 7, z = blockIdx.z;

    int k0s, k0e;
    const __nv_bfloat16 *bh, *bl;
    if (kslice) {
        k0s = z * kslice; k0e = k0s + kslice;
        bh = b_hi; bl = b_lo;
    } else {
        k0s = 0; k0e = K;
        bh = b_hi + (size_t)z * b_zstr;
        bl = b_lo + (size_t)z * b_zstr;
    }

    const int mW = (wid >> 1) << 5;      // 0/32/64/96
    const int nW = (wid & 1) << 5;       // 0/32
    const int grp = lane >> 2, qid = lane & 3;
    const int lane7 = lane & 7, l8 = (lane >> 3) & 1, l16 = (lane >> 4) & 1;
    const int aOff = (lane7 + l8 * 8) * STR + l16 * 8;
    const int bOff = (lane7 + l16 * 8) * STR + l8 * 8;

    float acc[2][4][4] = {};

    for (int k0 = k0s; k0 < k0e; k0 += 64) {
#pragma unroll
        for (int it = 0; it < 4; it++) {
            const int i = it * 256 + tid;
            const int r = i >> 3, c8 = (i & 7) << 3;
            const size_t ga = (size_t)(mBase + r) * K + k0 + c8;
            const int so = r * STR + c8;
            *(uint4*)(Ah + so) = *(const uint4*)(a_hi + ga);
            *(uint4*)(Al + so) = *(const uint4*)(a_lo + ga);
        }
#pragma unroll
        for (int it = 0; it < 2; it++) {
            const int i = it * 256 + tid;
            const int r = i >> 3, c8 = (i & 7) << 3;
            const size_t gb = (size_t)(nBase + r) * K + k0 + c8;
            const int so = r * STR + c8;
            *(uint4*)(Bh + so) = *(const uint4*)(bh + gb);
            *(uint4*)(Bl + so) = *(const uint4*)(bl + gb);
        }
        __syncthreads();

#pragma unroll
        for (int kk = 0; kk < 4; kk++) {
            const int kc = kk << 4;
            uint32_t ah[2][4], al[2][4], bhf[4][2], blf[4][2], t4[4];
#pragma unroll
            for (int mi = 0; mi < 2; mi++) {
                ldm4(ah[mi], Ah + (mW + mi * 16) * STR + kc + aOff);
                ldm4(al[mi], Al + (mW + mi * 16) * STR + kc + aOff);
            }
#pragma unroll
            for (int p = 0; p < 2; p++) {
                ldm4(t4, Bh + (nW + p * 16) * STR + kc + bOff);
                bhf[p * 2][0] = t4[0]; bhf[p * 2][1] = t4[1];
                bhf[p * 2 + 1][0] = t4[2]; bhf[p * 2 + 1][1] = t4[3];
                ldm4(t4, Bl + (nW + p * 16) * STR + kc + bOff);
                blf[p * 2][0] = t4[0]; blf[p * 2][1] = t4[1];
                blf[p * 2 + 1][0] = t4[2]; blf[p * 2 + 1][1] = t4[3];
            }
#pragma unroll
            for (int mi = 0; mi < 2; mi++)
#pragma unroll
                for (int ni = 0; ni < 4; ni++) {
                    mma16816(acc[mi][ni], ah[mi], bhf[ni]);
                    mma16816(acc[mi][ni], ah[mi], blf[ni]);
                    mma16816(acc[mi][ni], al[mi], bhf[ni]);
                }
        }
        __syncthreads();
    }

    float* Cz = C + (size_t)z * c_zstr;
    const float* brow = kslice ? nullptr : bias + (size_t)z * bias_zstr;
#pragma unroll
    for (int mi = 0; mi < 2; mi++) {
        const int r0 = mBase + mW + mi * 16 + grp;
#pragma unroll
        for (int ni = 0; ni < 4; ni++) {
            const int c = nBase + nW + ni * 8 + qid * 2;
            float b0 = 0.f, b1 = 0.f;
            if (brow) { b0 = brow[c]; b1 = brow[c + 1]; }
            if (r0 < m_valid) {
                float2 v = {acc[mi][ni][0] + b0, acc[mi][ni][1] + b1};
                *(float2*)(Cz + (size_t)r0 * c_row + c) = v;
            }
            if (r0 + 8 < m_valid) {
                float2 v = {acc[mi][ni][2] + b0, acc[mi][ni][3] + b1};
                *(float2*)(Cz + (size_t)(r0 + 8) * c_row + c) = v;
            }
        }
    }
}

// sum 16 q-head partials (128-row blocks, first 64 rows valid) + bias
__global__ void reduce16(const float* __restrict__ part, const float* __restrict__ bias,
                         float* __restrict__ C, int N)
{
    const int i = blockIdx.x * 256 + threadIdx.x;
    if (i >= BATCH * N) return;
    const int m = i / N, n = i - m * N;
    float s = bias[n];
#pragma unroll
    for (int zz = 0; zz < 16; zz++) s += part[(size_t)zz * 128 * N + (size_t)m * N + n];
    C[i] = s;
}

// ======================= fp32 split-K GEMM (M=64) ==========================
#define BN 64
#define BK 16
#define PAD 68
__global__ void __launch_bounds__(256) gemm_nt_splitk(
    const float* __restrict__ A, const float* __restrict__ W,
    float* __restrict__ Cpart, int N, int K)
{
    __shared__ float As[BK][PAD];
    __shared__ float Ws[BK][PAD];
    const int tid = threadIdx.x;
    const int tx = tid & 15, ty = tid >> 4;
    const int nBase = blockIdx.x * BN;
    const int z = blockIdx.z;
    const int kc = K >> 3;
    const int lr = tid >> 2;
    const int lc = (tid & 3) << 2;
    const float* Ap = A + (size_t)lr * K + lc;
    const float* Wp = W + (size_t)(nBase + lr) * K + lc;
    float acc[4][4] = {};
    const int kEnd = z * kc + kc;
    for (int k0 = z * kc; k0 < kEnd; k0 += BK) {
        float4 a4 = *(const float4*)(Ap + k0);
        float4 w4 = *(const float4*)(Wp + k0);
        As[lc + 0][lr] = a4.x; As[lc + 1][lr] = a4.y;
        As[lc + 2][lr] = a4.z; As[lc + 3][lr] = a4.w;
        Ws[lc + 0][lr] = w4.x; Ws[lc + 1][lr] = w4.y;
        Ws[lc + 2][lr] = w4.z; Ws[lc + 3][lr] = w4.w;
        __syncthreads();
#pragma unroll
        for (int kk = 0; kk < BK; kk++) {
            float4 av = *(const float4*)&As[kk][ty << 2];
            float4 wv = *(const float4*)&Ws[kk][tx << 2];
            float am[4] = {av.x, av.y, av.z, av.w};
            float wm[4] = {wv.x, wv.y, wv.z, wv.w};
#pragma unroll
            for (int i = 0; i < 4; i++)
#pragma unroll
                for (int j = 0; j < 4; j++)
                    acc[i][j] += am[i] * wm[j];
        }
        __syncthreads();
    }
    float* Cp = Cpart + (size_t)z * BATCH * N;
#pragma unroll
    for (int i = 0; i < 4; i++) {
        const int m = (ty << 2) + i;
#pragma unroll
        for (int j = 0; j < 4; j++) {
            const int n = nBase + (tx << 2) + j;
            Cp[(size_t)m * N + n] = acc[i][j];
        }
    }
}

__global__ void reduce8(const float* __restrict__ part, const float* __restrict__ bias,
                        float* __restrict__ C, int MN, int N, float alpha)
{
    const int i = blockIdx.x * 256 + threadIdx.x;
    if (i >= MN) return;
    float s = bias[i % N];
#pragma unroll
    for (int z = 0; z < 8; z++) s += part[(size_t)z * MN + i];
    C[i] = alpha * s;
}

// ======================= batched-query attention ===========================
__global__ void __launch_bounds__(256) attn2(
    const float* __restrict__ qp, const float* __restrict__ Kp,
    const float* __restrict__ Vp, const unsigned char* __restrict__ mask,
    float* __restrict__ o, int d)
{
    extern __shared__ float smf[];
    float* qs = smf;                 // 512
    float* sc = smf + 512;           // 16384
    float* ts = smf + 512 + 16384;   // 64*65

    const int h = blockIdx.x, b0 = blockIdx.y << 3;
    const int base = h << 6;
    const int tid = threadIdx.x, lane = tid & 31, wid = tid >> 5;

    for (int i = tid; i < 512; i += 256) {
        int qq = i >> 6, k = i & 63;
        qs[i] = qp[(size_t)(b0 + qq) * d + base + k];
    }
    __syncthreads();

    const float4* qs4 = (const float4*)(qs + (wid << 6));
    const unsigned char* mrow = mask + (size_t)(b0 + wid) * MEM;

    for (int mc = 0; mc < MEM; mc += 64) {
        for (int i = tid; i < 64 * 64; i += 256) {
            int r = i >> 6, c = i & 63;
            ts[r * 65 + c] = Kp[(size_t)(mc + r) * d + base + c];
        }
        __syncthreads();
        float acc0 = 0.f, acc1 = 0.f;
        const float* t0 = ts + lane * 65;
        const float* t1 = ts + (lane + 32) * 65;
#pragma unroll
        for (int k4 = 0; k4 < 16; k4++) {
            float4 qv = qs4[k4];
            acc0 += qv.x * t0[k4 * 4] + qv.y * t0[k4 * 4 + 1] + qv.z * t0[k4 * 4 + 2] + qv.w * t0[k4 * 4 + 3];
            acc1 += qv.x * t1[k4 * 4] + qv.y * t1[k4 * 4 + 1] + qv.z * t1[k4 * 4 + 2] + qv.w * t1[k4 * 4 + 3];
        }
        sc[(wid << 11) + mc + lane]      = mrow[mc + lane]      ? -1e9f : acc0;
        sc[(wid << 11) + mc + 32 + lane] = mrow[mc + 32 + lane] ? -1e9f : acc1;
        __syncthreads();
    }

    float* row = sc + (wid << 11);
    float mx = -1e30f;
    for (int i = lane; i < MEM; i += 32) mx = fmaxf(mx, row[i]);
#pragma unroll
    for (int off = 16; off; off >>= 1) mx = fmaxf(mx, __shfl_xor_sync(0xffffffffu, mx, off));
    float sum = 0.f;
    for (int i = lane; i < MEM; i += 32) {
        float e = __expf(row[i] - mx);
        row[i] = e;
        sum += e;
    }
#pragma unroll
    for (int off = 16; off; off >>= 1) sum += __shfl_xor_sync(0xffffffffu, sum, off);
    const float inv = 1.f / sum;

    float acc0 = 0.f, acc1 = 0.f;
    for (int mc = 0; mc < MEM; mc += 64) {
        __syncthreads();
        for (int i = tid; i < 64 * 64; i += 256) {
            int r = i >> 6, c = i & 63;
            ts[r * 65 + c] = Vp[(size_t)(mc + r) * d + base + c];
        }
        __syncthreads();
        const float* pr = row + mc;
#pragma unroll 8
        for (int j = 0; j < 64; j++) {
            float p = pr[j];
            acc0 += p * ts[j * 65 + lane];
            acc1 += p * ts[j * 65 + lane + 32];
        }
    }
    o[(size_t)(b0 + wid) * d + base + lane]      = acc0 * inv;
    o[(size_t)(b0 + wid) * d + base + lane + 32] = acc1 * inv;
}

// ======================= LayerNorm =========================================
__global__ void __launch_bounds__(256) ln_kernel(
    const float* __restrict__ x, const float* __restrict__ g,
    const float* __restrict__ be, float* __restrict__ out)
{
    __shared__ float rs[8], rss[8];
    __shared__ float s_mu, s_inv;
    const int rowi = blockIdx.x;
    const float4* xr = (const float4*)(x + (size_t)rowi * DLLM);
    const int tid = threadIdx.x, lane = tid & 31, warp = tid >> 5;
    float s = 0.f, ss = 0.f;
    for (int i = tid; i < DLLM / 4; i += 256) {
        float4 v = xr[i];
        s  += v.x + v.y + v.z + v.w;
        ss += v.x * v.x + v.y * v.y + v.z * v.z + v.w * v.w;
    }
#pragma unroll
    for (int off = 16; off; off >>= 1) {
        s  += __shfl_xor_sync(0xffffffffu, s, off);
        ss += __shfl_xor_sync(0xffffffffu, ss, off);
    }
    if (lane == 0) { rs[warp] = s; rss[warp] = ss; }
    __syncthreads();
    if (tid == 0) {
        float S = 0.f, SS = 0.f;
#pragma unroll
        for (int w = 0; w < 8; w++) { S += rs[w]; SS += rss[w]; }
        const float mu = S * (1.0f / DLLM);
        const float var = SS * (1.0f / DLLM) - mu * mu;
        s_mu = mu;
        s_inv = rsqrtf(var + 1e-5f);
    }
    __syncthreads();
    const float mu = s_mu, inv = s_inv;
    const float4* g4 = (const float4*)g;
    const float4* b4 = (const float4*)be;
    float4* outr = (float4*)(out + (size_t)rowi * DLLM);
    for (int i = tid; i < DLLM / 4; i += 256) {
        float4 v = xr[i], gv = g4[i], bv = b4[i];
        float4 r;
        r.x = (v.x - mu) * inv * gv.x + bv.x;
        r.y = (v.y - mu) * inv * gv.y + bv.y;
        r.z = (v.z - mu) * inv * gv.z + bv.z;
        r.w = (v.w - mu) * inv * gv.w + bv.w;
        outr[i] = r;
    }
}

// ======================= streams/events (created at init) ==================
struct StreamInit {
    cudaStream_t sA[3], sB[3];
    cudaEvent_t evH, evKV[3], evWL[3], evD[3];
    StreamInit() {
        for (int i = 0; i < 3; i++) {
            cudaStreamCreateWithFlags(&sA[i], cudaStreamNonBlocking);
            cudaStreamCreateWithFlags(&sB[i], cudaStreamNonBlocking);
            cudaEventCreateWithFlags(&evKV[i], cudaEventDisableTiming);
            cudaEventCreateWithFlags(&evWL[i], cudaEventDisableTiming);
            cudaEventCreateWithFlags(&evD[i], cudaEventDisableTiming);
        }
        cudaEventCreateWithFlags(&evH, cudaEventDisableTiming);
    }
};
static StreamInit g_si;

// ======================= host orchestration ================================
extern "C" void kernel_launch(void* const* d_in, const int* in_sizes, int n_in,
                              void* d_out, int out_size)
{
    const float* hidden = (const float*)d_in[0];
    const float* fibers[3] = {(const float*)d_in[1], (const float*)d_in[2], (const float*)d_in[3]};
    const unsigned char* mask = (const unsigned char*)d_in[4];
    const float* Wq[3]    = {(const float*)d_in[5],  (const float*)d_in[7],  (const float*)d_in[9]};
    const float* bq[3]    = {(const float*)d_in[6],  (const float*)d_in[8],  (const float*)d_in[10]};
    const float* Wqkv[3]  = {(const float*)d_in[11], (const float*)d_in[15], (const float*)d_in[19]};
    const float* bqkv[3]  = {(const float*)d_in[12], (const float*)d_in[16], (const float*)d_in[20]};
    const float* Wo[3]    = {(const float*)d_in[13], (const float*)d_in[17], (const float*)d_in[21]};
    const float* bo[3]    = {(const float*)d_in[14], (const float*)d_in[18], (const float*)d_in[22]};
    const float* Wlift[3] = {(const float*)d_in[23], (const float*)d_in[25], (const float*)d_in[27]};
    const float* blift[3] = {(const float*)d_in[24], (const float*)d_in[26], (const float*)d_in[28]};
    const float* lng = (const float*)d_in[29];
    const float* lnb = (const float*)d_in[30];

    const int ds[3]       = {256, 512, 1024};
    const int nhs[3]      = {4, 8, 16};
    const int slots[3]    = {4, 8, 4};
    const int slotBase[3] = {0, 4, 12};
    // per-bundle element offsets
    const size_t fOff[3]  = {0, 2048ull * 256, 2048ull * 768};
    const size_t qOff[3]  = {0, 256ull * 4096, 768ull * 4096};
    const size_t kvOff[3] = {0, 131072, 655360};
    const size_t wlOff[3] = {0, 4194304, 20971520};
    const size_t kvfOff[3]= {0, 1048576, 3145728};
    const size_t bOff[3]  = {0, 16384, 49152};
    const size_t pOff[3]  = {0, 32768, 98304};
    const size_t qpOff[3] = {0, 524288, 1572864};
    const size_t skOff[3] = {0, 131072, 393216};

    float *prefix, *kvf, *qb, *qp, *oo, *o2, *qpart, *skpart;
    __nv_bfloat16 *hidh, *hidl, *fh, *fl, *wqh, *wql, *wkvh, *wkvl, *wlh, *wll, *o2h, *o2l;
    cudaGetSymbolAddress((void**)&prefix, g_prefix);
    cudaGetSymbolAddress((void**)&kvf, g_kvf);
    cudaGetSymbolAddress((void**)&qb, g_qb);
    cudaGetSymbolAddress((void**)&qp, g_qp);
    cudaGetSymbolAddress((void**)&oo, g_o);
    cudaGetSymbolAddress((void**)&o2, g_o2);
    cudaGetSymbolAddress((void**)&qpart, g_qpart);
    cudaGetSymbolAddress((void**)&skpart, g_skpart);
    cudaGetSymbolAddress((void**)&hidh, g_hidh);
    cudaGetSymbolAddress((void**)&hidl, g_hidl);
    cudaGetSymbolAddress((void**)&fh, g_fh);
    cudaGetSymbolAddress((void**)&fl, g_fl);
    cudaGetSymbolAddress((void**)&wqh, g_wqh);
    cudaGetSymbolAddress((void**)&wql, g_wql);
    cudaGetSymbolAddress((void**)&wkvh, g_wkvh);
    cudaGetSymbolAddress((void**)&wkvl, g_wkvl);
    cudaGetSymbolAddress((void**)&wlh, g_wlh);
    cudaGetSymbolAddress((void**)&wll, g_wll);
    cudaGetSymbolAddress((void**)&o2h, g_o2h);
    cudaGetSymbolAddress((void**)&o2l, g_o2l);

    cudaFuncSetAttribute(hmma_k, cudaFuncAttributeMaxDynamicSharedMemorySize, HMMA_SMEM);
    cudaFuncSetAttribute(attn2, cudaFuncAttributeMaxDynamicSharedMemorySize, 21056 * 4);

    // hidden -> hi/lo (padded to 128 rows), then fork
    cvt_hilo_pad<<<(128 * DLLM) / 256, 256>>>(hidden, hidh, hidl, BATCH, DLLM);
    cudaEventRecord(g_si.evH, 0);

    for (int b = 0; b < 3; b++) {
        const int d = ds[b], nh = nhs[b], s = slots[b];
        const int MN = BATCH * d;
        const int rblocks = (MN + 255) / 256;
        cudaStream_t A = g_si.sA[b], Bs = g_si.sB[b];

        // ---- stream A: fibers/weights for KV, KV projection, Wlift transpose
        cudaStreamWaitEvent(A, g_si.evH, 0);
        cvt_hilo<<<(MEM * d + 255) / 256, 256, 0, A>>>(fibers[b], fh + fOff[b], fl + fOff[b], MEM * d);
        cvt_hilo<<<(2 * d * d + 255) / 256, 256, 0, A>>>(Wqkv[b] + (size_t)d * d,
                                                         wkvh + kvOff[b], wkvl + kvOff[b], 2 * d * d);
        hmma_k<<<dim3(d / 64, MEM / 128, 2), 256, HMMA_SMEM, A>>>(
            fh + fOff[b], fl + fOff[b], wkvh + kvOff[b], wkvl + kvOff[b],
            bqkv[b] + d, d, kvf + kvfOff[b], d, (long long)MEM * d,
            (long long)d * d, d, MEM, 0);
        cudaEventRecord(g_si.evKV[b], A);
        transp_hilo<<<dim3(DLLM / 32, d / 32, s), dim3(32, 8), 0, A>>>(
            Wlift[b], wlh + wlOff[b], wll + wlOff[b], d);
        cudaEventRecord(g_si.evWL[b], A);

        // ---- stream B: q chain -> attention -> out-proj -> lift
        cudaStreamWaitEvent(Bs, g_si.evH, 0);
        cvt_hilo<<<(d * DLLM + 255) / 256, 256, 0, Bs>>>(Wq[b], wqh + qOff[b], wql + qOff[b], d * DLLM);
        hmma_k<<<dim3(d / 64, 1, 16), 256, HMMA_SMEM, Bs>>>(
            hidh, hidl, wqh + qOff[b], wql + qOff[b],
            nullptr, 0, qpart + qpOff[b], d, (long long)128 * d, 0, DLLM, 128, 256);
        reduce16<<<rblocks, 256, 0, Bs>>>(qpart + qpOff[b], bq[b], qb + bOff[b], d);
        gemm_nt_splitk<<<dim3(d / 64, 1, 8), 256, 0, Bs>>>(qb + bOff[b], Wqkv[b], skpart + skOff[b], d, d);
        reduce8<<<rblocks, 256, 0, Bs>>>(skpart + skOff[b], bqkv[b], qp + bOff[b], MN, d, 0.125f);
        cudaStreamWaitEvent(Bs, g_si.evKV[b], 0);
        attn2<<<dim3(nh, BATCH / 8), 256, 21056 * 4, Bs>>>(
            qp + bOff[b], kvf + kvfOff[b], kvf + kvfOff[b] + (size_t)MEM * d, mask, oo + bOff[b], d);
        gemm_nt_splitk<<<dim3(d / 64, 1, 8), 256, 0, Bs>>>(oo + bOff[b], Wo[b], skpart + skOff[b], d, d);
        reduce8<<<rblocks, 256, 0, Bs>>>(skpart + skOff[b], bo[b], o2 + bOff[b], MN, d, 1.0f);
        cvt_hilo_pad<<<(128 * d + 255) / 256, 256, 0, Bs>>>(o2 + bOff[b], o2h + pOff[b], o2l + pOff[b], BATCH, d);
        cudaStreamWaitEvent(Bs, g_si.evWL[b], 0);
        hmma_k<<<dim3(DLLM / 64, 1, s), 256, HMMA_SMEM, Bs>>>(
            o2h + pOff[b], o2l + pOff[b], wlh + wlOff[b], wll + wlOff[b],
            blift[b], DLLM, prefix + (size_t)slotBase[b] * DLLM, 16 * DLLM, DLLM,
            (long long)DLLM * d, d, BATCH, 0);
        cudaEventRecord(g_si.evD[b], Bs);
    }

    // join + LayerNorm
    for (int b = 0; b < 3; b++) cudaStreamWaitEvent(0, g_si.evD[b], 0);
    ln_kernel<<<BATCH * 16, 256>>>(prefix, lng, lnb, (float*)d_out);
}

// round 8
// speedup vs baseline: 1.9798x; 1.0929x over previous
#include <cuda_runtime.h>
#include <cuda_bf16.h>
#include <cstdint>

// ---------------------------------------------------------------------------
// CrossBundleAttention — fused fp32->bf16(hi/lo) HMMA GEMMs, multi-stream
// B=64, M=2048, D_LLM=4096, bundles: (d=256,nh=4,s=4) (512,8,8) (1024,16,4)
// ---------------------------------------------------------------------------

#define BATCH 64
#define MEM   2048
#define DLLM  4096
#define STR   72      // smem row stride (bf16): 64 data + 8 pad

// ======================= scratch (device globals) ==========================
__device__ float g_prefix[4194304];
__device__ float g_kvf[7340032];                 // per-bundle K|V fp32
__device__ float g_qb[114688], g_qp[114688], g_o[114688], g_o2[114688];
__device__ float g_qpart[3670016];               // q-head split-K partials
__device__ float g_skpart[917504];               // small split-K partials

// ======================= HMMA helpers ======================================
__device__ __forceinline__ void mma16816(float* c, const uint32_t* a, const uint32_t* b) {
    asm volatile(
        "mma.sync.aligned.m16n8k16.row.col.f32.bf16.bf16.f32 "
        "{%0,%1,%2,%3}, {%4,%5,%6,%7}, {%8,%9}, {%0,%1,%2,%3};"
        : "+f"(c[0]), "+f"(c[1]), "+f"(c[2]), "+f"(c[3])
        : "r"(a[0]), "r"(a[1]), "r"(a[2]), "r"(a[3]), "r"(b[0]), "r"(b[1]));
}
__device__ __forceinline__ void ldm4(uint32_t* r, const __nv_bfloat16* p) {
    uint32_t a = (uint32_t)__cvta_generic_to_shared(p);
    asm volatile("ldmatrix.sync.aligned.m8n8.x4.shared.b16 {%0,%1,%2,%3}, [%4];"
        : "=r"(r[0]), "=r"(r[1]), "=r"(r[2]), "=r"(r[3]) : "r"(a));
}
__device__ __forceinline__ uint32_t pack2(__nv_bfloat16 a, __nv_bfloat16 b) {
    __nv_bfloat162 p(a, b);           // a -> low halfword (lower address)
    return *(uint32_t*)&p;
}
// float4 -> 4 hi bf16 (hh) + 4 lo bf16 (ll)
__device__ __forceinline__ void cvt4(float4 v, uint2& hh, uint2& ll) {
    __nv_bfloat16 h0 = __float2bfloat16(v.x), h1 = __float2bfloat16(v.y);
    __nv_bfloat16 h2 = __float2bfloat16(v.z), h3 = __float2bfloat16(v.w);
    __nv_bfloat16 l0 = __float2bfloat16(v.x - __bfloat162float(h0));
    __nv_bfloat16 l1 = __float2bfloat16(v.y - __bfloat162float(h1));
    __nv_bfloat16 l2 = __float2bfloat16(v.z - __bfloat162float(h2));
    __nv_bfloat16 l3 = __float2bfloat16(v.w - __bfloat162float(h3));
    hh.x = pack2(h0, h1); hh.y = pack2(h2, h3);
    ll.x = pack2(l0, l1); ll.y = pack2(l2, l3);
}

#define HMMA_SMEM ((2 * 128 * STR + 2 * 64 * STR) * 2)   // 55296 B

// ---------------------------------------------------------------------------
// Fused-conversion hi/lo HMMA GEMM. Block tile 128x64, 8 warps, warp 32x32.
// A: fp32 (a_rows, K) row-major; rows >= a_rows treated as zero.
// transB==0: B fp32 (N, K) row-major; z selects B slice (b_zstr) unless kslice.
// transB==1: B fp32 (K, N_total) row-major (ldb = N_total); z selects slice.
// kslice>0:  z = K-slice index (K-split partials into C[z]); B shared, no bias.
// C[z][m][n] (+ bias[z][n] when kslice==0).
// ---------------------------------------------------------------------------
__global__ void __launch_bounds__(256) hmma_f32(
    const float* __restrict__ A, const float* __restrict__ Bm,
    const float* __restrict__ bias, long long bias_zstr,
    float* __restrict__ C, long long c_row, long long c_zstr,
    long long b_zstr, int K, int ldb, int a_rows, int m_valid,
    int kslice, int transB)
{
    extern __shared__ __nv_bfloat16 sm[];
    __nv_bfloat16* Ah = sm;
    __nv_bfloat16* Al = sm + 128 * STR;
    __nv_bfloat16* Bh = sm + 2 * 128 * STR;
    __nv_bfloat16* Bl = Bh + 64 * STR;

    const int tid = threadIdx.x, wid = tid >> 5, lane = tid & 31;
    const int nBase = blockIdx.x << 6, mBase = blockIdx.y << 7, z = blockIdx.z;

    int k0s, k0e;
    const float* bp;
    if (kslice) {
        k0s = z * kslice; k0e = k0s + kslice;
        bp = Bm;
    } else {
        k0s = 0; k0e = K;
        bp = Bm + (size_t)z * b_zstr;
    }

    const int mW = (wid >> 1) << 5;      // 0/32/64/96
    const int nW = (wid & 1) << 5;       // 0/32
    const int grp = lane >> 2, qid = lane & 3;
    const int lane7 = lane & 7, l8 = (lane >> 3) & 1, l16 = (lane >> 4) & 1;
    const int aOff = (lane7 + l8 * 8) * STR + l16 * 8;
    const int bOff = (lane7 + l16 * 8) * STR + l8 * 8;

    float acc[2][4][4] = {};

    for (int k0 = k0s; k0 < k0e; k0 += 64) {
        // ---- stage A: 128 x 64 fp32 -> hi/lo bf16 ----
#pragma unroll
        for (int it = 0; it < 8; it++) {
            const int i = it * 256 + tid;
            const int r = i >> 4, c4 = (i & 15) << 2;
            float4 v = make_float4(0.f, 0.f, 0.f, 0.f);
            if (mBase + r < a_rows)
                v = *(const float4*)(A + (size_t)(mBase + r) * K + k0 + c4);
            uint2 hh, ll;
            cvt4(v, hh, ll);
            *(uint2*)(Ah + r * STR + c4) = hh;
            *(uint2*)(Al + r * STR + c4) = ll;
        }
        // ---- stage B: 64 x 64 ----
        if (!transB) {
#pragma unroll
            for (int it = 0; it < 4; it++) {
                const int i = it * 256 + tid;
                const int r = i >> 4, c4 = (i & 15) << 2;
                float4 v = *(const float4*)(bp + (size_t)(nBase + r) * K + k0 + c4);
                uint2 hh, ll;
                cvt4(v, hh, ll);
                *(uint2*)(Bh + r * STR + c4) = hh;
                *(uint2*)(Bl + r * STR + c4) = ll;
            }
        } else {
#pragma unroll
            for (int it = 0; it < 4; it++) {
                const int i = it * 256 + tid;
                const int kr = i >> 4, c4 = (i & 15) << 2;
                float4 v = *(const float4*)(bp + (size_t)(k0 + kr) * ldb + nBase + c4);
                const float vv[4] = {v.x, v.y, v.z, v.w};
#pragma unroll
                for (int j = 0; j < 4; j++) {
                    __nv_bfloat16 h = __float2bfloat16(vv[j]);
                    Bh[(c4 + j) * STR + kr] = h;
                    Bl[(c4 + j) * STR + kr] = __float2bfloat16(vv[j] - __bfloat162float(h));
                }
            }
        }
        __syncthreads();

#pragma unroll
        for (int kk = 0; kk < 4; kk++) {
            const int kc = kk << 4;
            uint32_t ah[2][4], al[2][4], bhf[4][2], blf[4][2], t4[4];
#pragma unroll
            for (int mi = 0; mi < 2; mi++) {
                ldm4(ah[mi], Ah + (mW + mi * 16) * STR + kc + aOff);
                ldm4(al[mi], Al + (mW + mi * 16) * STR + kc + aOff);
            }
#pragma unroll
            for (int p = 0; p < 2; p++) {
                ldm4(t4, Bh + (nW + p * 16) * STR + kc + bOff);
                bhf[p * 2][0] = t4[0]; bhf[p * 2][1] = t4[1];
                bhf[p * 2 + 1][0] = t4[2]; bhf[p * 2 + 1][1] = t4[3];
                ldm4(t4, Bl + (nW + p * 16) * STR + kc + bOff);
                blf[p * 2][0] = t4[0]; blf[p * 2][1] = t4[1];
                blf[p * 2 + 1][0] = t4[2]; blf[p * 2 + 1][1] = t4[3];
            }
#pragma unroll
            for (int mi = 0; mi < 2; mi++)
#pragma unroll
                for (int ni = 0; ni < 4; ni++) {
                    mma16816(acc[mi][ni], ah[mi], bhf[ni]);
                    mma16816(acc[mi][ni], ah[mi], blf[ni]);
                    mma16816(acc[mi][ni], al[mi], bhf[ni]);
                }
        }
        __syncthreads();
    }

    float* Cz = C + (size_t)z * c_zstr;
    const float* brow = kslice ? nullptr : bias + (size_t)z * bias_zstr;
#pragma unroll
    for (int mi = 0; mi < 2; mi++) {
        const int r0 = mBase + mW + mi * 16 + grp;
#pragma unroll
        for (int ni = 0; ni < 4; ni++) {
            const int c = nBase + nW + ni * 8 + qid * 2;
            float b0 = 0.f, b1 = 0.f;
            if (brow) { b0 = brow[c]; b1 = brow[c + 1]; }
            if (r0 < m_valid) {
                float2 v = {acc[mi][ni][0] + b0, acc[mi][ni][1] + b1};
                *(float2*)(Cz + (size_t)r0 * c_row + c) = v;
            }
            if (r0 + 8 < m_valid) {
                float2 v = {acc[mi][ni][2] + b0, acc[mi][ni][3] + b1};
                *(float2*)(Cz + (size_t)(r0 + 8) * c_row + c) = v;
            }
        }
    }
}

// sum 16 q-head partials (128-row blocks, first 64 rows valid) + bias
__global__ void reduce16(const float* __restrict__ part, const float* __restrict__ bias,
                         float* __restrict__ C, int N)
{
    const int i = blockIdx.x * 256 + threadIdx.x;
    if (i >= BATCH * N) return;
    const int m = i / N, n = i - m * N;
    float s = bias[n];
#pragma unroll
    for (int zz = 0; zz < 16; zz++) s += part[(size_t)zz * 128 * N + (size_t)m * N + n];
    C[i] = s;
}

// ======================= fp32 split-K GEMM (M=64) ==========================
#define BN 64
#define BK 16
#define PAD 68
__global__ void __launch_bounds__(256) gemm_nt_splitk(
    const float* __restrict__ A, const float* __restrict__ W,
    float* __restrict__ Cpart, int N, int K)
{
    __shared__ float As[BK][PAD];
    __shared__ float Ws[BK][PAD];
    const int tid = threadIdx.x;
    const int tx = tid & 15, ty = tid >> 4;
    const int nBase = blockIdx.x * BN;
    const int z = blockIdx.z;
    const int kc = K >> 3;
    const int lr = tid >> 2;
    const int lc = (tid & 3) << 2;
    const float* Ap = A + (size_t)lr * K + lc;
    const float* Wp = W + (size_t)(nBase + lr) * K + lc;
    float acc[4][4] = {};
    const int kEnd = z * kc + kc;
    for (int k0 = z * kc; k0 < kEnd; k0 += BK) {
        float4 a4 = *(const float4*)(Ap + k0);
        float4 w4 = *(const float4*)(Wp + k0);
        As[lc + 0][lr] = a4.x; As[lc + 1][lr] = a4.y;
        As[lc + 2][lr] = a4.z; As[lc + 3][lr] = a4.w;
        Ws[lc + 0][lr] = w4.x; Ws[lc + 1][lr] = w4.y;
        Ws[lc + 2][lr] = w4.z; Ws[lc + 3][lr] = w4.w;
        __syncthreads();
#pragma unroll
        for (int kk = 0; kk < BK; kk++) {
            float4 av = *(const float4*)&As[kk][ty << 2];
            float4 wv = *(const float4*)&Ws[kk][tx << 2];
            float am[4] = {av.x, av.y, av.z, av.w};
            float wm[4] = {wv.x, wv.y, wv.z, wv.w};
#pragma unroll
            for (int i = 0; i < 4; i++)
#pragma unroll
                for (int j = 0; j < 4; j++)
                    acc[i][j] += am[i] * wm[j];
        }
        __syncthreads();
    }
    float* Cp = Cpart + (size_t)z * BATCH * N;
#pragma unroll
    for (int i = 0; i < 4; i++) {
        const int m = (ty << 2) + i;
#pragma unroll
        for (int j = 0; j < 4; j++) {
            const int n = nBase + (tx << 2) + j;
            Cp[(size_t)m * N + n] = acc[i][j];
        }
    }
}

__global__ void reduce8(const float* __restrict__ part, const float* __restrict__ bias,
                        float* __restrict__ C, int MN, int N, float alpha)
{
    const int i = blockIdx.x * 256 + threadIdx.x;
    if (i >= MN) return;
    float s = bias[i % N];
#pragma unroll
    for (int z = 0; z < 8; z++) s += part[(size_t)z * MN + i];
    C[i] = alpha * s;
}

// ======================= batched-query attention ===========================
__global__ void __launch_bounds__(256) attn2(
    const float* __restrict__ qp, const float* __restrict__ Kp,
    const float* __restrict__ Vp, const unsigned char* __restrict__ mask,
    float* __restrict__ o, int d)
{
    extern __shared__ float smf[];
    float* qs = smf;                 // 512
    float* sc = smf + 512;           // 16384
    float* ts = smf + 512 + 16384;   // 64*65

    const int h = blockIdx.x, b0 = blockIdx.y << 3;
    const int base = h << 6;
    const int tid = threadIdx.x, lane = tid & 31, wid = tid >> 5;

    for (int i = tid; i < 512; i += 256) {
        int qq = i >> 6, k = i & 63;
        qs[i] = qp[(size_t)(b0 + qq) * d + base + k];
    }
    __syncthreads();

    const float4* qs4 = (const float4*)(qs + (wid << 6));
    const unsigned char* mrow = mask + (size_t)(b0 + wid) * MEM;

    for (int mc = 0; mc < MEM; mc += 64) {
        for (int i = tid; i < 64 * 64; i += 256) {
            int r = i >> 6, c = i & 63;
            ts[r * 65 + c] = Kp[(size_t)(mc + r) * d + base + c];
        }
        __syncthreads();
        float acc0 = 0.f, acc1 = 0.f;
        const float* t0 = ts + lane * 65;
        const float* t1 = ts + (lane + 32) * 65;
#pragma unroll
        for (int k4 = 0; k4 < 16; k4++) {
            float4 qv = qs4[k4];
            acc0 += qv.x * t0[k4 * 4] + qv.y * t0[k4 * 4 + 1] + qv.z * t0[k4 * 4 + 2] + qv.w * t0[k4 * 4 + 3];
            acc1 += qv.x * t1[k4 * 4] + qv.y * t1[k4 * 4 + 1] + qv.z * t1[k4 * 4 + 2] + qv.w * t1[k4 * 4 + 3];
        }
        sc[(wid << 11) + mc + lane]      = mrow[mc + lane]      ? -1e9f : acc0;
        sc[(wid << 11) + mc + 32 + lane] = mrow[mc + 32 + lane] ? -1e9f : acc1;
        __syncthreads();
    }

    float* row = sc + (wid << 11);
    float mx = -1e30f;
    for (int i = lane; i < MEM; i += 32) mx = fmaxf(mx, row[i]);
#pragma unroll
    for (int off = 16; off; off >>= 1) mx = fmaxf(mx, __shfl_xor_sync(0xffffffffu, mx, off));
    float sum = 0.f;
    for (int i = lane; i < MEM; i += 32) {
        float e = __expf(row[i] - mx);
        row[i] = e;
        sum += e;
    }
#pragma unroll
    for (int off = 16; off; off >>= 1) sum += __shfl_xor_sync(0xffffffffu, sum, off);
    const float inv = 1.f / sum;

    float acc0 = 0.f, acc1 = 0.f;
    for (int mc = 0; mc < MEM; mc += 64) {
        __syncthreads();
        for (int i = tid; i < 64 * 64; i += 256) {
            int r = i >> 6, c = i & 63;
            ts[r * 65 + c] = Vp[(size_t)(mc + r) * d + base + c];
        }
        __syncthreads();
        const float* pr = row + mc;
#pragma unroll 8
        for (int j = 0; j < 64; j++) {
            float p = pr[j];
            acc0 += p * ts[j * 65 + lane];
            acc1 += p * ts[j * 65 + lane + 32];
        }
    }
    o[(size_t)(b0 + wid) * d + base + lane]      = acc0 * inv;
    o[(size_t)(b0 + wid) * d + base + lane + 32] = acc1 * inv;
}

// ======================= LayerNorm =========================================
__global__ void __launch_bounds__(256) ln_kernel(
    const float* __restrict__ x, const float* __restrict__ g,
    const float* __restrict__ be, float* __restrict__ out)
{
    __shared__ float rs[8], rss[8];
    __shared__ float s_mu, s_inv;
    const int rowi = blockIdx.x;
    const float4* xr = (const float4*)(x + (size_t)rowi * DLLM);
    const int tid = threadIdx.x, lane = tid & 31, warp = tid >> 5;
    float s = 0.f, ss = 0.f;
    for (int i = tid; i < DLLM / 4; i += 256) {
        float4 v = xr[i];
        s  += v.x + v.y + v.z + v.w;
        ss += v.x * v.x + v.y * v.y + v.z * v.z + v.w * v.w;
    }
#pragma unroll
    for (int off = 16; off; off >>= 1) {
        s  += __shfl_xor_sync(0xffffffffu, s, off);
        ss += __shfl_xor_sync(0xffffffffu, ss, off);
    }
    if (lane == 0) { rs[warp] = s; rss[warp] = ss; }
    __syncthreads();
    if (tid == 0) {
        float S = 0.f, SS = 0.f;
#pragma unroll
        for (int w = 0; w < 8; w++) { S += rs[w]; SS += rss[w]; }
        const float mu = S * (1.0f / DLLM);
        const float var = SS * (1.0f / DLLM) - mu * mu;
        s_mu = mu;
        s_inv = rsqrtf(var + 1e-5f);
    }
    __syncthreads();
    const float mu = s_mu, inv = s_inv;
    const float4* g4 = (const float4*)g;
    const float4* b4 = (const float4*)be;
    float4* outr = (float4*)(out + (size_t)rowi * DLLM);
    for (int i = tid; i < DLLM / 4; i += 256) {
        float4 v = xr[i], gv = g4[i], bv = b4[i];
        float4 r;
        r.x = (v.x - mu) * inv * gv.x + bv.x;
        r.y = (v.y - mu) * inv * gv.y + bv.y;
        r.z = (v.z - mu) * inv * gv.z + bv.z;
        r.w = (v.w - mu) * inv * gv.w + bv.w;
        outr[i] = r;
    }
}

// ======================= streams/events (created at init) ==================
struct StreamInit {
    cudaStream_t sA[3], sB[3];
    cudaEvent_t evFork, evKV[3], evD[3];
    StreamInit() {
        for (int i = 0; i < 3; i++) {
            cudaStreamCreateWithFlags(&sA[i], cudaStreamNonBlocking);
            cudaStreamCreateWithFlags(&sB[i], cudaStreamNonBlocking);
            cudaEventCreateWithFlags(&evKV[i], cudaEventDisableTiming);
            cudaEventCreateWithFlags(&evD[i], cudaEventDisableTiming);
        }
        cudaEventCreateWithFlags(&evFork, cudaEventDisableTiming);
    }
};
static StreamInit g_si;

// tiny no-op kernel to root the capture graph on the capture stream
__global__ void fork_kernel() {}

// ======================= host orchestration ================================
extern "C" void kernel_launch(void* const* d_in, const int* in_sizes, int n_in,
                              void* d_out, int out_size)
{
    const float* hidden = (const float*)d_in[0];
    const float* fibers[3] = {(const float*)d_in[1], (const float*)d_in[2], (const float*)d_in[3]};
    const unsigned char* mask = (const unsigned char*)d_in[4];
    const float* Wq[3]    = {(const float*)d_in[5],  (const float*)d_in[7],  (const float*)d_in[9]};
    const float* bq[3]    = {(const float*)d_in[6],  (const float*)d_in[8],  (const float*)d_in[10]};
    const float* Wqkv[3]  = {(const float*)d_in[11], (const float*)d_in[15], (const float*)d_in[19]};
    const float* bqkv[3]  = {(const float*)d_in[12], (const float*)d_in[16], (const float*)d_in[20]};
    const float* Wo[3]    = {(const float*)d_in[13], (const float*)d_in[17], (const float*)d_in[21]};
    const float* bo[3]    = {(const float*)d_in[14], (const float*)d_in[18], (const float*)d_in[22]};
    const float* Wlift[3] = {(const float*)d_in[23], (const float*)d_in[25], (const float*)d_in[27]};
    const float* blift[3] = {(const float*)d_in[24], (const float*)d_in[26], (const float*)d_in[28]};
    const float* lng = (const float*)d_in[29];
    const float* lnb = (const float*)d_in[30];

    const int ds[3]       = {256, 512, 1024};
    const int nhs[3]      = {4, 8, 16};
    const int slots[3]    = {4, 8, 4};
    const int slotBase[3] = {0, 4, 12};
    const size_t kvfOff[3]= {0, 1048576, 3145728};
    const size_t bOff[3]  = {0, 16384, 49152};
    const size_t qpOff[3] = {0, 524288, 1572864};
    const size_t skOff[3] = {0, 131072, 393216};

    float *prefix, *kvf, *qb, *qp, *oo, *o2, *qpart, *skpart;
    cudaGetSymbolAddress((void**)&prefix, g_prefix);
    cudaGetSymbolAddress((void**)&kvf, g_kvf);
    cudaGetSymbolAddress((void**)&qb, g_qb);
    cudaGetSymbolAddress((void**)&qp, g_qp);
    cudaGetSymbolAddress((void**)&oo, g_o);
    cudaGetSymbolAddress((void**)&o2, g_o2);
    cudaGetSymbolAddress((void**)&qpart, g_qpart);
    cudaGetSymbolAddress((void**)&skpart, g_skpart);

    cudaFuncSetAttribute(hmma_f32, cudaFuncAttributeMaxDynamicSharedMemorySize, HMMA_SMEM);
    cudaFuncSetAttribute(attn2, cudaFuncAttributeMaxDynamicSharedMemorySize, 21056 * 4);

    // Root the capture on the capture stream, then fork side streams from it.
    fork_kernel<<<1, 32>>>();
    cudaEventRecord(g_si.evFork, 0);

    for (int b = 0; b < 3; b++) {
        const int d = ds[b], nh = nhs[b], s = slots[b];
        const int MN = BATCH * d;
        const int rblocks = (MN + 255) / 256;
        cudaStream_t A = g_si.sA[b], Bs = g_si.sB[b];

        // ---- stream A: KV projection (fused conversion) ----
        cudaStreamWaitEvent(A, g_si.evFork, 0);
        hmma_f32<<<dim3(d / 64, MEM / 128, 2), 256, HMMA_SMEM, A>>>(
            fibers[b], Wqkv[b] + (size_t)d * d, bqkv[b] + d, /*bias_zstr=*/d,
            kvf + kvfOff[b], /*c_row=*/d, /*c_zstr=*/(long long)MEM * d,
            /*b_zstr=*/(long long)d * d, /*K=*/d, /*ldb=*/d,
            /*a_rows=*/MEM, /*m_valid=*/MEM, /*kslice=*/0, /*transB=*/0);
        cudaEventRecord(g_si.evKV[b], A);

        // ---- stream B: q chain -> attention -> out-proj -> lift ----
        cudaStreamWaitEvent(Bs, g_si.evFork, 0);
        hmma_f32<<<dim3(d / 64, 1, 16), 256, HMMA_SMEM, Bs>>>(
            hidden, Wq[b], /*bias=*/nullptr, /*bias_zstr=*/0,
            qpart + qpOff[b], /*c_row=*/d, /*c_zstr=*/(long long)128 * d,
            /*b_zstr=*/0, /*K=*/DLLM, /*ldb=*/DLLM,
            /*a_rows=*/BATCH, /*m_valid=*/128, /*kslice=*/256, /*transB=*/0);
        reduce16<<<rblocks, 256, 0, Bs>>>(qpart + qpOff[b], bq[b], qb + bOff[b], d);
        gemm_nt_splitk<<<dim3(d / 64, 1, 8), 256, 0, Bs>>>(qb + bOff[b], Wqkv[b], skpart + skOff[b], d, d);
        reduce8<<<rblocks, 256, 0, Bs>>>(skpart + skOff[b], bqkv[b], qp + bOff[b], MN, d, 0.125f);
        cudaStreamWaitEvent(Bs, g_si.evKV[b], 0);
        attn2<<<dim3(nh, BATCH / 8), 256, 21056 * 4, Bs>>>(
            qp + bOff[b], kvf + kvfOff[b], kvf + kvfOff[b] + (size_t)MEM * d, mask, oo + bOff[b], d);
        gemm_nt_splitk<<<dim3(d / 64, 1, 8), 256, 0, Bs>>>(oo + bOff[b], Wo[b], skpart + skOff[b], d, d);
        reduce8<<<rblocks, 256, 0, Bs>>>(skpart + skOff[b], bo[b], o2 + bOff[b], MN, d, 1.0f);
        hmma_f32<<<dim3(DLLM / 64, 1, s), 256, HMMA_SMEM, Bs>>>(
            o2 + bOff[b], Wlift[b], blift[b], /*bias_zstr=*/DLLM,
            prefix + (size_t)slotBase[b] * DLLM, /*c_row=*/16 * DLLM, /*c_zstr=*/DLLM,
            /*b_zstr=*/(long long)d * DLLM, /*K=*/d, /*ldb=*/DLLM,
            /*a_rows=*/BATCH, /*m_valid=*/BATCH, /*kslice=*/0, /*transB=*/1);
        cudaEventRecord(g_si.evD[b], Bs);
    }

    for (int b = 0; b < 3; b++) cudaStreamWaitEvent(0, g_si.evD[b], 0);
    ln_kernel<<<BATCH * 16, 256>>>(prefix, lng, lnb, (float*)d_out);
}

// round 9
// speedup vs baseline: 2.1146x; 1.0680x over previous
#include <cuda_runtime.h>
#include <cuda_bf16.h>
#include <cstdint>

// ---------------------------------------------------------------------------
// CrossBundleAttention — prefetched hi/lo HMMA everywhere, multi-stream
// B=64, M=2048, D_LLM=4096, bundles: (d=256,nh=4,s=4) (512,8,8) (1024,16,4)
// ---------------------------------------------------------------------------

#define BATCH 64
#define MEM   2048
#define DLLM  4096
#define STR   72      // smem row stride (bf16): 64 data + 8 pad

// ======================= scratch (device globals) ==========================
__device__ float g_prefix[4194304];
__device__ float g_kvf[7340032];                 // per-bundle K|V fp32
__device__ float g_qb[114688], g_qp[114688], g_o[114688], g_o2[114688];
__device__ float g_part[3670016];                // split-K partials (64-row slices)

// ======================= HMMA helpers ======================================
__device__ __forceinline__ void mma16816(float* c, const uint32_t* a, const uint32_t* b) {
    asm volatile(
        "mma.sync.aligned.m16n8k16.row.col.f32.bf16.bf16.f32 "
        "{%0,%1,%2,%3}, {%4,%5,%6,%7}, {%8,%9}, {%0,%1,%2,%3};"
        : "+f"(c[0]), "+f"(c[1]), "+f"(c[2]), "+f"(c[3])
        : "r"(a[0]), "r"(a[1]), "r"(a[2]), "r"(a[3]), "r"(b[0]), "r"(b[1]));
}
__device__ __forceinline__ void ldm4(uint32_t* r, const __nv_bfloat16* p) {
    uint32_t a = (uint32_t)__cvta_generic_to_shared(p);
    asm volatile("ldmatrix.sync.aligned.m8n8.x4.shared.b16 {%0,%1,%2,%3}, [%4];"
        : "=r"(r[0]), "=r"(r[1]), "=r"(r[2]), "=r"(r[3]) : "r"(a));
}
__device__ __forceinline__ uint32_t pack2(__nv_bfloat16 a, __nv_bfloat16 b) {
    __nv_bfloat162 p(a, b);
    return *(uint32_t*)&p;
}
__device__ __forceinline__ void cvt4(float4 v, uint2& hh, uint2& ll) {
    __nv_bfloat16 h0 = __float2bfloat16(v.x), h1 = __float2bfloat16(v.y);
    __nv_bfloat16 h2 = __float2bfloat16(v.z), h3 = __float2bfloat16(v.w);
    __nv_bfloat16 l0 = __float2bfloat16(v.x - __bfloat162float(h0));
    __nv_bfloat16 l1 = __float2bfloat16(v.y - __bfloat162float(h1));
    __nv_bfloat16 l2 = __float2bfloat16(v.z - __bfloat162float(h2));
    __nv_bfloat16 l3 = __float2bfloat16(v.w - __bfloat162float(h3));
    hh.x = pack2(h0, h1); hh.y = pack2(h2, h3);
    ll.x = pack2(l0, l1); ll.y = pack2(l2, l3);
}

#define HMMA_SMEM ((2 * 128 * STR + 2 * 64 * STR) * 2)   // 55296 B

// ---------------------------------------------------------------------------
// Fused-conversion hi/lo HMMA GEMM with register prefetch.
// A: fp32 (a_rows, K) row-major; rows >= a_rows read as zero.
// transB==0: B fp32 (N, K) row-major; z selects B slice (b_zstr) unless kslice.
// transB==1: B fp32 (K, ldb) row-major; nBase indexes columns.
// kslice>0:  z = K-slice index; partials into C[z] (64-row slices), no bias.
// ---------------------------------------------------------------------------
__global__ void __launch_bounds__(256) hmma_f32(
    const float* __restrict__ A, const float* __restrict__ Bm,
    const float* __restrict__ bias, long long bias_zstr,
    float* __restrict__ C, long long c_row, long long c_zstr,
    long long b_zstr, int K, int ldb, int a_rows, int m_valid,
    int kslice, int transB)
{
    extern __shared__ __nv_bfloat16 sm[];
    __nv_bfloat16* Ah = sm;
    __nv_bfloat16* Al = sm + 128 * STR;
    __nv_bfloat16* Bh = sm + 2 * 128 * STR;
    __nv_bfloat16* Bl = Bh + 64 * STR;

    const int tid = threadIdx.x, wid = tid >> 5, lane = tid & 31;
    const int nBase = blockIdx.x << 6, mBase = blockIdx.y << 7, z = blockIdx.z;

    int k0s, k0e;
    const float* bp;
    if (kslice) {
        k0s = z * kslice; k0e = k0s + kslice;
        bp = Bm;
    } else {
        k0s = 0; k0e = K;
        bp = Bm + (size_t)z * b_zstr;
    }

    const int mW = (wid >> 1) << 5;
    const int nW = (wid & 1) << 5;
    const int grp = lane >> 2, qid = lane & 3;
    const int lane7 = lane & 7, l8 = (lane >> 3) & 1, l16 = (lane >> 4) & 1;
    const int aOff = (lane7 + l8 * 8) * STR + l16 * 8;
    const int bOff = (lane7 + l16 * 8) * STR + l8 * 8;

    // per-thread staging coordinates
    const int ar = tid >> 4, ac4 = (tid & 15) << 2;     // A: rows ar, ar+16, ..
    float acc[2][4][4] = {};
    float4 pa[8], pb[4];

    // ---- prefetch lambdas ----
    auto loadA = [&](int k0) {
#pragma unroll
        for (int it = 0; it < 8; it++) {
            const int r = ar + it * 16;
            if (mBase + r < a_rows)
                pa[it] = *(const float4*)(A + (size_t)(mBase + r) * K + k0 + ac4);
            else
                pa[it] = make_float4(0.f, 0.f, 0.f, 0.f);
        }
    };
    auto loadB = [&](int k0) {
        if (!transB) {
#pragma unroll
            for (int it = 0; it < 4; it++) {
                const int r = ar + it * 16;
                pb[it] = *(const float4*)(bp + (size_t)(nBase + r) * K + k0 + ac4);
            }
        } else {
#pragma unroll
            for (int it = 0; it < 4; it++) {
                const int kr = ar + it * 16;
                pb[it] = *(const float4*)(bp + (size_t)(k0 + kr) * ldb + nBase + ac4);
            }
        }
    };
    auto storeAB = [&]() {
#pragma unroll
        for (int it = 0; it < 8; it++) {
            const int r = ar + it * 16;
            uint2 hh, ll;
            cvt4(pa[it], hh, ll);
            *(uint2*)(Ah + r * STR + ac4) = hh;
            *(uint2*)(Al + r * STR + ac4) = ll;
        }
        if (!transB) {
#pragma unroll
            for (int it = 0; it < 4; it++) {
                const int r = ar + it * 16;
                uint2 hh, ll;
                cvt4(pb[it], hh, ll);
                *(uint2*)(Bh + r * STR + ac4) = hh;
                *(uint2*)(Bl + r * STR + ac4) = ll;
            }
        } else {
#pragma unroll
            for (int it = 0; it < 4; it++) {
                const int kr = ar + it * 16;
                const float vv[4] = {pb[it].x, pb[it].y, pb[it].z, pb[it].w};
#pragma unroll
                for (int j = 0; j < 4; j++) {
                    __nv_bfloat16 h = __float2bfloat16(vv[j]);
                    Bh[(ac4 + j) * STR + kr] = h;
                    Bl[(ac4 + j) * STR + kr] = __float2bfloat16(vv[j] - __bfloat162float(h));
                }
            }
        }
    };

    loadA(k0s);
    loadB(k0s);

    for (int k0 = k0s; k0 < k0e; k0 += 64) {
        __syncthreads();       // previous chunk's compute done; smem reusable
        storeAB();
        __syncthreads();
        if (k0 + 64 < k0e) {   // issue next chunk's gmem loads early
            loadA(k0 + 64);
            loadB(k0 + 64);
        }

#pragma unroll
        for (int kk = 0; kk < 4; kk++) {
            const int kc = kk << 4;
            uint32_t ah[2][4], al[2][4], bhf[4][2], blf[4][2], t4[4];
#pragma unroll
            for (int mi = 0; mi < 2; mi++) {
                ldm4(ah[mi], Ah + (mW + mi * 16) * STR + kc + aOff);
                ldm4(al[mi], Al + (mW + mi * 16) * STR + kc + aOff);
            }
#pragma unroll
            for (int p = 0; p < 2; p++) {
                ldm4(t4, Bh + (nW + p * 16) * STR + kc + bOff);
                bhf[p * 2][0] = t4[0]; bhf[p * 2][1] = t4[1];
                bhf[p * 2 + 1][0] = t4[2]; bhf[p * 2 + 1][1] = t4[3];
                ldm4(t4, Bl + (nW + p * 16) * STR + kc + bOff);
                blf[p * 2][0] = t4[0]; blf[p * 2][1] = t4[1];
                blf[p * 2 + 1][0] = t4[2]; blf[p * 2 + 1][1] = t4[3];
            }
#pragma unroll
            for (int mi = 0; mi < 2; mi++)
#pragma unroll
                for (int ni = 0; ni < 4; ni++) {
                    mma16816(acc[mi][ni], ah[mi], bhf[ni]);
                    mma16816(acc[mi][ni], ah[mi], blf[ni]);
                    mma16816(acc[mi][ni], al[mi], bhf[ni]);
                }
        }
    }

    float* Cz = C + (size_t)z * c_zstr;
    const float* brow = kslice ? nullptr : bias + (size_t)z * bias_zstr;
#pragma unroll
    for (int mi = 0; mi < 2; mi++) {
        const int r0 = mBase + mW + mi * 16 + grp;
#pragma unroll
        for (int ni = 0; ni < 4; ni++) {
            const int c = nBase + nW + ni * 8 + qid * 2;
            float b0 = 0.f, b1 = 0.f;
            if (brow) { b0 = brow[c]; b1 = brow[c + 1]; }
            if (r0 < m_valid) {
                float2 v = {acc[mi][ni][0] + b0, acc[mi][ni][1] + b1};
                *(float2*)(Cz + (size_t)r0 * c_row + c) = v;
            }
            if (r0 + 8 < m_valid) {
                float2 v = {acc[mi][ni][2] + b0, acc[mi][ni][3] + b1};
                *(float2*)(Cz + (size_t)(r0 + 8) * c_row + c) = v;
            }
        }
    }
}

// sum nz 64-row partial slices + bias, scale by alpha
__global__ void reduceZ(const float* __restrict__ part, const float* __restrict__ bias,
                        float* __restrict__ C, int N, int nz, float alpha)
{
    const int i = blockIdx.x * 256 + threadIdx.x;
    if (i >= BATCH * N) return;
    const int n = i % N;
    float s = bias[n];
    for (int z = 0; z < nz; z++) s += part[(size_t)z * BATCH * N + i];
    C[i] = alpha * s;
}

// ======================= batched-query attention ===========================
__global__ void __launch_bounds__(256) attn2(
    const float* __restrict__ qp, const float* __restrict__ Kp,
    const float* __restrict__ Vp, const unsigned char* __restrict__ mask,
    float* __restrict__ o, int d)
{
    extern __shared__ float smf[];
    float* qs = smf;                 // 512
    float* sc = smf + 512;           // 16384
    float* ts = smf + 512 + 16384;   // 64*65

    const int h = blockIdx.x, b0 = blockIdx.y << 3;
    const int base = h << 6;
    const int tid = threadIdx.x, lane = tid & 31, wid = tid >> 5;

    for (int i = tid; i < 512; i += 256) {
        int qq = i >> 6, k = i & 63;
        qs[i] = qp[(size_t)(b0 + qq) * d + base + k];
    }
    __syncthreads();

    const float4* qs4 = (const float4*)(qs + (wid << 6));
    const unsigned char* mrow = mask + (size_t)(b0 + wid) * MEM;

    for (int mc = 0; mc < MEM; mc += 64) {
        for (int i = tid; i < 64 * 16; i += 256) {       // float4 staging
            int r = i >> 4, c4 = (i & 15) << 2;
            float4 v = *(const float4*)(Kp + (size_t)(mc + r) * d + base + c4);
            float* dst = ts + r * 65 + c4;
            dst[0] = v.x; dst[1] = v.y; dst[2] = v.z; dst[3] = v.w;
        }
        __syncthreads();
        float acc0 = 0.f, acc1 = 0.f;
        const float* t0 = ts + lane * 65;
        const float* t1 = ts + (lane + 32) * 65;
#pragma unroll
        for (int k4 = 0; k4 < 16; k4++) {
            float4 qv = qs4[k4];
            acc0 += qv.x * t0[k4 * 4] + qv.y * t0[k4 * 4 + 1] + qv.z * t0[k4 * 4 + 2] + qv.w * t0[k4 * 4 + 3];
            acc1 += qv.x * t1[k4 * 4] + qv.y * t1[k4 * 4 + 1] + qv.z * t1[k4 * 4 + 2] + qv.w * t1[k4 * 4 + 3];
        }
        sc[(wid << 11) + mc + lane]      = mrow[mc + lane]      ? -1e9f : acc0;
        sc[(wid << 11) + mc + 32 + lane] = mrow[mc + 32 + lane] ? -1e9f : acc1;
        __syncthreads();
    }

    float* row = sc + (wid << 11);
    float mx = -1e30f;
    for (int i = lane; i < MEM; i += 32) mx = fmaxf(mx, row[i]);
#pragma unroll
    for (int off = 16; off; off >>= 1) mx = fmaxf(mx, __shfl_xor_sync(0xffffffffu, mx, off));
    float sum = 0.f;
    for (int i = lane; i < MEM; i += 32) {
        float e = __expf(row[i] - mx);
        row[i] = e;
        sum += e;
    }
#pragma unroll
    for (int off = 16; off; off >>= 1) sum += __shfl_xor_sync(0xffffffffu, sum, off);
    const float inv = 1.f / sum;

    float acc0 = 0.f, acc1 = 0.f;
    for (int mc = 0; mc < MEM; mc += 64) {
        __syncthreads();
        for (int i = tid; i < 64 * 16; i += 256) {       // float4 staging
            int r = i >> 4, c4 = (i & 15) << 2;
            float4 v = *(const float4*)(Vp + (size_t)(mc + r) * d + base + c4);
            float* dst = ts + r * 65 + c4;
            dst[0] = v.x; dst[1] = v.y; dst[2] = v.z; dst[3] = v.w;
        }
        __syncthreads();
        const float* pr = row + mc;
#pragma unroll 8
        for (int j = 0; j < 64; j++) {
            float p = pr[j];
            acc0 += p * ts[j * 65 + lane];
            acc1 += p * ts[j * 65 + lane + 32];
        }
    }
    o[(size_t)(b0 + wid) * d + base + lane]      = acc0 * inv;
    o[(size_t)(b0 + wid) * d + base + lane + 32] = acc1 * inv;
}

// ======================= LayerNorm =========================================
__global__ void __launch_bounds__(256) ln_kernel(
    const float* __restrict__ x, const float* __restrict__ g,
    const float* __restrict__ be, float* __restrict__ out)
{
    __shared__ float rs[8], rss[8];
    __shared__ float s_mu, s_inv;
    const int rowi = blockIdx.x;
    const float4* xr = (const float4*)(x + (size_t)rowi * DLLM);
    const int tid = threadIdx.x, lane = tid & 31, warp = tid >> 5;
    float s = 0.f, ss = 0.f;
    for (int i = tid; i < DLLM / 4; i += 256) {
        float4 v = xr[i];
        s  += v.x + v.y + v.z + v.w;
        ss += v.x * v.x + v.y * v.y + v.z * v.z + v.w * v.w;
    }
#pragma unroll
    for (int off = 16; off; off >>= 1) {
        s  += __shfl_xor_sync(0xffffffffu, s, off);
        ss += __shfl_xor_sync(0xffffffffu, ss, off);
    }
    if (lane == 0) { rs[warp] = s; rss[warp] = ss; }
    __syncthreads();
    if (tid == 0) {
        float S = 0.f, SS = 0.f;
#pragma unroll
        for (int w = 0; w < 8; w++) { S += rs[w]; SS += rss[w]; }
        const float mu = S * (1.0f / DLLM);
        const float var = SS * (1.0f / DLLM) - mu * mu;
        s_mu = mu;
        s_inv = rsqrtf(var + 1e-5f);
    }
    __syncthreads();
    const float mu = s_mu, inv = s_inv;
    const float4* g4 = (const float4*)g;
    const float4* b4 = (const float4*)be;
    float4* outr = (float4*)(out + (size_t)rowi * DLLM);
    for (int i = tid; i < DLLM / 4; i += 256) {
        float4 v = xr[i], gv = g4[i], bv = b4[i];
        float4 r;
        r.x = (v.x - mu) * inv * gv.x + bv.x;
        r.y = (v.y - mu) * inv * gv.y + bv.y;
        r.z = (v.z - mu) * inv * gv.z + bv.z;
        r.w = (v.w - mu) * inv * gv.w + bv.w;
        outr[i] = r;
    }
}

// ======================= streams/events (created at init) ==================
struct StreamInit {
    cudaStream_t sA[3], sB[3];
    cudaEvent_t evFork, evKV[3], evD[3];
    StreamInit() {
        for (int i = 0; i < 3; i++) {
            cudaStreamCreateWithFlags(&sA[i], cudaStreamNonBlocking);
            cudaStreamCreateWithFlags(&sB[i], cudaStreamNonBlocking);
            cudaEventCreateWithFlags(&evKV[i], cudaEventDisableTiming);
            cudaEventCreateWithFlags(&evD[i], cudaEventDisableTiming);
        }
        cudaEventCreateWithFlags(&evFork, cudaEventDisableTiming);
    }
};
static StreamInit g_si;

__global__ void fork_kernel() {}

// ======================= host orchestration ================================
extern "C" void kernel_launch(void* const* d_in, const int* in_sizes, int n_in,
                              void* d_out, int out_size)
{
    const float* hidden = (const float*)d_in[0];
    const float* fibers[3] = {(const float*)d_in[1], (const float*)d_in[2], (const float*)d_in[3]};
    const unsigned char* mask = (const unsigned char*)d_in[4];
    const float* Wq[3]    = {(const float*)d_in[5],  (const float*)d_in[7],  (const float*)d_in[9]};
    const float* bq[3]    = {(const float*)d_in[6],  (const float*)d_in[8],  (const float*)d_in[10]};
    const float* Wqkv[3]  = {(const float*)d_in[11], (const float*)d_in[15], (const float*)d_in[19]};
    const float* bqkv[3]  = {(const float*)d_in[12], (const float*)d_in[16], (const float*)d_in[20]};
    const float* Wo[3]    = {(const float*)d_in[13], (const float*)d_in[17], (const float*)d_in[21]};
    const float* bo[3]    = {(const float*)d_in[14], (const float*)d_in[18], (const float*)d_in[22]};
    const float* Wlift[3] = {(const float*)d_in[23], (const float*)d_in[25], (const float*)d_in[27]};
    const float* blift[3] = {(const float*)d_in[24], (const float*)d_in[26], (const float*)d_in[28]};
    const float* lng = (const float*)d_in[29];
    const float* lnb = (const float*)d_in[30];

    const int ds[3]       = {256, 512, 1024};
    const int nhs[3]      = {4, 8, 16};
    const int slots[3]    = {4, 8, 4};
    const int slotBase[3] = {0, 4, 12};
    const size_t kvfOff[3]= {0, 1048576, 3145728};
    const size_t bOff[3]  = {0, 16384, 49152};
    const size_t ptOff[3] = {0, 524288, 1572864};   // partials per bundle

    float *prefix, *kvf, *qb, *qp, *oo, *o2, *part;
    cudaGetSymbolAddress((void**)&prefix, g_prefix);
    cudaGetSymbolAddress((void**)&kvf, g_kvf);
    cudaGetSymbolAddress((void**)&qb, g_qb);
    cudaGetSymbolAddress((void**)&qp, g_qp);
    cudaGetSymbolAddress((void**)&oo, g_o);
    cudaGetSymbolAddress((void**)&o2, g_o2);
    cudaGetSymbolAddress((void**)&part, g_part);

    cudaFuncSetAttribute(hmma_f32, cudaFuncAttributeMaxDynamicSharedMemorySize, HMMA_SMEM);
    cudaFuncSetAttribute(attn2, cudaFuncAttributeMaxDynamicSharedMemorySize, 21056 * 4);

    fork_kernel<<<1, 32>>>();
    cudaEventRecord(g_si.evFork, 0);

    for (int b = 0; b < 3; b++) {
        const int d = ds[b], nh = nhs[b], s = slots[b];
        const int MN = BATCH * d;
        const int rblocks = (MN + 255) / 256;
        cudaStream_t A = g_si.sA[b], Bs = g_si.sB[b];

        // ---- stream A: KV projection ----
        cudaStreamWaitEvent(A, g_si.evFork, 0);
        hmma_f32<<<dim3(d / 64, MEM / 128, 2), 256, HMMA_SMEM, A>>>(
            fibers[b], Wqkv[b] + (size_t)d * d, bqkv[b] + d, d,
            kvf + kvfOff[b], d, (long long)MEM * d,
            (long long)d * d, d, d, MEM, MEM, 0, 0);
        cudaEventRecord(g_si.evKV[b], A);

        // ---- stream B: q chain -> attention -> out-proj -> lift ----
        cudaStreamWaitEvent(Bs, g_si.evFork, 0);
        // q-head: K=4096 split 16x256
        hmma_f32<<<dim3(d / 64, 1, 16), 256, HMMA_SMEM, Bs>>>(
            hidden, Wq[b], nullptr, 0,
            part + ptOff[b], d, (long long)BATCH * d,
            0, DLLM, DLLM, BATCH, BATCH, 256, 0);
        reduceZ<<<rblocks, 256, 0, Bs>>>(part + ptOff[b], bq[b], qb + bOff[b], d, 16, 1.0f);
        // q in-proj: K=d split 4x(d/4), scale 0.125 folded into reduce
        hmma_f32<<<dim3(d / 64, 1, 4), 256, HMMA_SMEM, Bs>>>(
            qb + bOff[b], Wqkv[b], nullptr, 0,
            part + ptOff[b], d, (long long)BATCH * d,
            0, d, d, BATCH, BATCH, d / 4, 0);
        reduceZ<<<rblocks, 256, 0, Bs>>>(part + ptOff[b], bqkv[b], qp + bOff[b], d, 4, 0.125f);
        cudaStreamWaitEvent(Bs, g_si.evKV[b], 0);
        attn2<<<dim3(nh, BATCH / 8), 256, 21056 * 4, Bs>>>(
            qp + bOff[b], kvf + kvfOff[b], kvf + kvfOff[b] + (size_t)MEM * d, mask, oo + bOff[b], d);
        // out-proj: K=d split 4x(d/4)
        hmma_f32<<<dim3(d / 64, 1, 4), 256, HMMA_SMEM, Bs>>>(
            oo + bOff[b], Wo[b], nullptr, 0,
            part + ptOff[b], d, (long long)BATCH * d,
            0, d, d, BATCH, BATCH, d / 4, 0);
        reduceZ<<<rblocks, 256, 0, Bs>>>(part + ptOff[b], bo[b], o2 + bOff[b], d, 4, 1.0f);
        // lift
        hmma_f32<<<dim3(DLLM / 64, 1, s), 256, HMMA_SMEM, Bs>>>(
            o2 + bOff[b], Wlift[b], blift[b], DLLM,
            prefix + (size_t)slotBase[b] * DLLM, 16 * DLLM, DLLM,
            (long long)d * DLLM, d, DLLM, BATCH, BATCH, 0, 1);
        cudaEventRecord(g_si.evD[b], Bs);
    }

    for (int b = 0; b < 3; b++) cudaStreamWaitEvent(0, g_si.evD[b], 0);
    ln_kernel<<<BATCH * 16, 256>>>(prefix, lng, lnb, (float*)d_out);
}

// round 10
// speedup vs baseline: 2.2937x; 1.0847x over previous
#include <cuda_runtime.h>
#include <cuda_bf16.h>
#include <cstdint>

// ---------------------------------------------------------------------------
// CrossBundleAttention — HMMA hi/lo GEMMs w/ atomic split-K, coop attention
// B=64, M=2048, D_LLM=4096, bundles: (d=256,nh=4,s=4) (512,8,8) (1024,16,4)
// ---------------------------------------------------------------------------

#define BATCH 64
#define MEM   2048
#define DLLM  4096
#define STR   72

// ======================= scratch (device globals) ==========================
__device__ float g_prefix[4194304];
__device__ float g_kvf[7340032];
__device__ float g_qb[114688], g_qp[114688], g_o[114688], g_o2[114688];

// ======================= HMMA helpers ======================================
__device__ __forceinline__ void mma16816(float* c, const uint32_t* a, const uint32_t* b) {
    asm volatile(
        "mma.sync.aligned.m16n8k16.row.col.f32.bf16.bf16.f32 "
        "{%0,%1,%2,%3}, {%4,%5,%6,%7}, {%8,%9}, {%0,%1,%2,%3};"
        : "+f"(c[0]), "+f"(c[1]), "+f"(c[2]), "+f"(c[3])
        : "r"(a[0]), "r"(a[1]), "r"(a[2]), "r"(a[3]), "r"(b[0]), "r"(b[1]));
}
__device__ __forceinline__ void ldm4(uint32_t* r, const __nv_bfloat16* p) {
    uint32_t a = (uint32_t)__cvta_generic_to_shared(p);
    asm volatile("ldmatrix.sync.aligned.m8n8.x4.shared.b16 {%0,%1,%2,%3}, [%4];"
        : "=r"(r[0]), "=r"(r[1]), "=r"(r[2]), "=r"(r[3]) : "r"(a));
}
__device__ __forceinline__ uint32_t pack2(__nv_bfloat16 a, __nv_bfloat16 b) {
    __nv_bfloat162 p(a, b);
    return *(uint32_t*)&p;
}
__device__ __forceinline__ void cvt4(float4 v, uint2& hh, uint2& ll) {
    __nv_bfloat16 h0 = __float2bfloat16(v.x), h1 = __float2bfloat16(v.y);
    __nv_bfloat16 h2 = __float2bfloat16(v.z), h3 = __float2bfloat16(v.w);
    __nv_bfloat16 l0 = __float2bfloat16(v.x - __bfloat162float(h0));
    __nv_bfloat16 l1 = __float2bfloat16(v.y - __bfloat162float(h1));
    __nv_bfloat16 l2 = __float2bfloat16(v.z - __bfloat162float(h2));
    __nv_bfloat16 l3 = __float2bfloat16(v.w - __bfloat162float(h3));
    hh.x = pack2(h0, h1); hh.y = pack2(h2, h3);
    ll.x = pack2(l0, l1); ll.y = pack2(l2, l3);
}

#define HMMA_SMEM ((2 * 128 * STR + 2 * 64 * STR) * 2)   // 55296 B

// ---------------------------------------------------------------------------
// Fused-conversion hi/lo HMMA GEMM with register prefetch.
// kslice==0: C[z][m][n] = acc + bias[z][n]   (z selects B slice via b_zstr)
// kslice>0 : z = K-slice; atomicAdd(C[m][n], alpha*acc) — C pre-filled w/ bias.
// ---------------------------------------------------------------------------
__global__ void __launch_bounds__(256) hmma_f32(
    const float* __restrict__ A, const float* __restrict__ Bm,
    const float* __restrict__ bias, long long bias_zstr,
    float* __restrict__ C, long long c_row, long long c_zstr,
    long long b_zstr, int K, int ldb, int a_rows, int m_valid,
    int kslice, int transB, float alpha)
{
    extern __shared__ __nv_bfloat16 sm[];
    __nv_bfloat16* Ah = sm;
    __nv_bfloat16* Al = sm + 128 * STR;
    __nv_bfloat16* Bh = sm + 2 * 128 * STR;
    __nv_bfloat16* Bl = Bh + 64 * STR;

    const int tid = threadIdx.x, wid = tid >> 5, lane = tid & 31;
    const int nBase = blockIdx.x << 6, mBase = blockIdx.y << 7, z = blockIdx.z;

    int k0s, k0e;
    const float* bp;
    if (kslice) {
        k0s = z * kslice; k0e = k0s + kslice;
        bp = Bm;
    } else {
        k0s = 0; k0e = K;
        bp = Bm + (size_t)z * b_zstr;
    }

    const int mW = (wid >> 1) << 5;
    const int nW = (wid & 1) << 5;
    const int grp = lane >> 2, qid = lane & 3;
    const int lane7 = lane & 7, l8 = (lane >> 3) & 1, l16 = (lane >> 4) & 1;
    const int aOff = (lane7 + l8 * 8) * STR + l16 * 8;
    const int bOff = (lane7 + l16 * 8) * STR + l8 * 8;

    const int ar = tid >> 4, ac4 = (tid & 15) << 2;
    float acc[2][4][4] = {};
    float4 pa[8], pb[4];

    auto loadA = [&](int k0) {
#pragma unroll
        for (int it = 0; it < 8; it++) {
            const int r = ar + it * 16;
            if (mBase + r < a_rows)
                pa[it] = *(const float4*)(A + (size_t)(mBase + r) * K + k0 + ac4);
            else
                pa[it] = make_float4(0.f, 0.f, 0.f, 0.f);
        }
    };
    auto loadB = [&](int k0) {
        if (!transB) {
#pragma unroll
            for (int it = 0; it < 4; it++) {
                const int r = ar + it * 16;
                pb[it] = *(const float4*)(bp + (size_t)(nBase + r) * K + k0 + ac4);
            }
        } else {
#pragma unroll
            for (int it = 0; it < 4; it++) {
                const int kr = ar + it * 16;
                pb[it] = *(const float4*)(bp + (size_t)(k0 + kr) * ldb + nBase + ac4);
            }
        }
    };
    auto storeAB = [&]() {
#pragma unroll
        for (int it = 0; it < 8; it++) {
            const int r = ar + it * 16;
            uint2 hh, ll;
            cvt4(pa[it], hh, ll);
            *(uint2*)(Ah + r * STR + ac4) = hh;
            *(uint2*)(Al + r * STR + ac4) = ll;
        }
        if (!transB) {
#pragma unroll
            for (int it = 0; it < 4; it++) {
                const int r = ar + it * 16;
                uint2 hh, ll;
                cvt4(pb[it], hh, ll);
                *(uint2*)(Bh + r * STR + ac4) = hh;
                *(uint2*)(Bl + r * STR + ac4) = ll;
            }
        } else {
#pragma unroll
            for (int it = 0; it < 4; it++) {
                const int kr = ar + it * 16;
                const float vv[4] = {pb[it].x, pb[it].y, pb[it].z, pb[it].w};
#pragma unroll
                for (int j = 0; j < 4; j++) {
                    __nv_bfloat16 h = __float2bfloat16(vv[j]);
                    Bh[(ac4 + j) * STR + kr] = h;
                    Bl[(ac4 + j) * STR + kr] = __float2bfloat16(vv[j] - __bfloat162float(h));
                }
            }
        }
    };

    loadA(k0s);
    loadB(k0s);

    for (int k0 = k0s; k0 < k0e; k0 += 64) {
        __syncthreads();
        storeAB();
        __syncthreads();
        if (k0 + 64 < k0e) {
            loadA(k0 + 64);
            loadB(k0 + 64);
        }

#pragma unroll
        for (int kk = 0; kk < 4; kk++) {
            const int kc = kk << 4;
            uint32_t ah[2][4], al[2][4], bhf[4][2], blf[4][2], t4[4];
#pragma unroll
            for (int mi = 0; mi < 2; mi++) {
                ldm4(ah[mi], Ah + (mW + mi * 16) * STR + kc + aOff);
                ldm4(al[mi], Al + (mW + mi * 16) * STR + kc + aOff);
            }
#pragma unroll
            for (int p = 0; p < 2; p++) {
                ldm4(t4, Bh + (nW + p * 16) * STR + kc + bOff);
                bhf[p * 2][0] = t4[0]; bhf[p * 2][1] = t4[1];
                bhf[p * 2 + 1][0] = t4[2]; bhf[p * 2 + 1][1] = t4[3];
                ldm4(t4, Bl + (nW + p * 16) * STR + kc + bOff);
                blf[p * 2][0] = t4[0]; blf[p * 2][1] = t4[1];
                blf[p * 2 + 1][0] = t4[2]; blf[p * 2 + 1][1] = t4[3];
            }
#pragma unroll
            for (int mi = 0; mi < 2; mi++)
#pragma unroll
                for (int ni = 0; ni < 4; ni++) {
                    mma16816(acc[mi][ni], ah[mi], bhf[ni]);
                    mma16816(acc[mi][ni], ah[mi], blf[ni]);
                    mma16816(acc[mi][ni], al[mi], bhf[ni]);
                }
        }
    }

    if (kslice) {
        // atomic accumulate into pre-biased C (no z offset)
#pragma unroll
        for (int mi = 0; mi < 2; mi++) {
            const int r0 = mBase + mW + mi * 16 + grp;
#pragma unroll
            for (int ni = 0; ni < 4; ni++) {
                const int c = nBase + nW + ni * 8 + qid * 2;
                if (r0 < m_valid) {
                    atomicAdd(C + (size_t)r0 * c_row + c,     alpha * acc[mi][ni][0]);
                    atomicAdd(C + (size_t)r0 * c_row + c + 1, alpha * acc[mi][ni][1]);
                }
                if (r0 + 8 < m_valid) {
                    atomicAdd(C + (size_t)(r0 + 8) * c_row + c,     alpha * acc[mi][ni][2]);
                    atomicAdd(C + (size_t)(r0 + 8) * c_row + c + 1, alpha * acc[mi][ni][3]);
                }
            }
        }
    } else {
        float* Cz = C + (size_t)z * c_zstr;
        const float* brow = bias + (size_t)z * bias_zstr;
#pragma unroll
        for (int mi = 0; mi < 2; mi++) {
            const int r0 = mBase + mW + mi * 16 + grp;
#pragma unroll
            for (int ni = 0; ni < 4; ni++) {
                const int c = nBase + nW + ni * 8 + qid * 2;
                const float b0 = brow[c], b1 = brow[c + 1];
                if (r0 < m_valid) {
                    float2 v = {acc[mi][ni][0] + b0, acc[mi][ni][1] + b1};
                    *(float2*)(Cz + (size_t)r0 * c_row + c) = v;
                }
                if (r0 + 8 < m_valid) {
                    float2 v = {acc[mi][ni][2] + b0, acc[mi][ni][3] + b1};
                    *(float2*)(Cz + (size_t)(r0 + 8) * c_row + c) = v;
                }
            }
        }
    }
}

// =============== graph root: fill qb/qp/o2 with (scaled) biases =============
__global__ void init_bias(float* __restrict__ qb, float* __restrict__ qp,
                          float* __restrict__ o2,
                          const float* bq0, const float* bq1, const float* bq2,
                          const float* bi0, const float* bi1, const float* bi2,
                          const float* bo0, const float* bo1, const float* bo2)
{
    const int i = blockIdx.x * 256 + threadIdx.x;
    if (i >= 114688) return;
    int n;
    const float *bqv, *biv, *bov;
    if (i < 16384)       { n = i & 255;             bqv = bq0; biv = bi0; bov = bo0; }
    else if (i < 49152)  { n = (i - 16384) & 511;   bqv = bq1; biv = bi1; bov = bo1; }
    else                 { n = (i - 49152) & 1023;  bqv = bq2; biv = bi2; bov = bo2; }
    qb[i] = bqv[n];
    qp[i] = 0.125f * biv[n];
    o2[i] = bov[n];
}

// ======================= batched-query attention ===========================
// smem: qs[512] | sc[16384] | ts[4160] | sinv[8]  = 21064 floats
__global__ void __launch_bounds__(256) attn2(
    const float* __restrict__ qp, const float* __restrict__ Kp,
    const float* __restrict__ Vp, const unsigned char* __restrict__ mask,
    float* __restrict__ o, int d)
{
    extern __shared__ float smf[];
    float* qs = smf;
    float* sc = smf + 512;
    float* ts = smf + 512 + 16384;
    float* sinv = ts + 4160;

    const int h = blockIdx.x, b0 = blockIdx.y << 3;
    const int base = h << 6;
    const int tid = threadIdx.x, lane = tid & 31, wid = tid >> 5;

    for (int i = tid; i < 512; i += 256) {
        int qq = i >> 6, k = i & 63;
        qs[i] = qp[(size_t)(b0 + qq) * d + base + k];
    }
    __syncthreads();

    const float4* qs4 = (const float4*)(qs + (wid << 6));
    const unsigned char* mrow = mask + (size_t)(b0 + wid) * MEM;

    // ---- phase 1: scores (warp = query) ----
    for (int mc = 0; mc < MEM; mc += 64) {
        for (int i = tid; i < 64 * 16; i += 256) {
            int r = i >> 4, c4 = (i & 15) << 2;
            float4 v = *(const float4*)(Kp + (size_t)(mc + r) * d + base + c4);
            float* dst = ts + r * 65 + c4;
            dst[0] = v.x; dst[1] = v.y; dst[2] = v.z; dst[3] = v.w;
        }
        __syncthreads();
        float acc0 = 0.f, acc1 = 0.f;
        const float* t0 = ts + lane * 65;
        const float* t1 = ts + (lane + 32) * 65;
#pragma unroll
        for (int k4 = 0; k4 < 16; k4++) {
            float4 qv = qs4[k4];
            acc0 += qv.x * t0[k4 * 4] + qv.y * t0[k4 * 4 + 1] + qv.z * t0[k4 * 4 + 2] + qv.w * t0[k4 * 4 + 3];
            acc1 += qv.x * t1[k4 * 4] + qv.y * t1[k4 * 4 + 1] + qv.z * t1[k4 * 4 + 2] + qv.w * t1[k4 * 4 + 3];
        }
        sc[(wid << 11) + mc + lane]      = mrow[mc + lane]      ? -1e9f : acc0;
        sc[(wid << 11) + mc + 32 + lane] = mrow[mc + 32 + lane] ? -1e9f : acc1;
        __syncthreads();
    }

    // ---- softmax (warp = query) ----
    float* row = sc + (wid << 11);
    float mx = -1e30f;
    for (int i = lane; i < MEM; i += 32) mx = fmaxf(mx, row[i]);
#pragma unroll
    for (int off = 16; off; off >>= 1) mx = fmaxf(mx, __shfl_xor_sync(0xffffffffu, mx, off));
    float sum = 0.f;
    for (int i = lane; i < MEM; i += 32) {
        float e = __expf(row[i] - mx);
        row[i] = e;
        sum += e;
    }
#pragma unroll
    for (int off = 16; off; off >>= 1) sum += __shfl_xor_sync(0xffffffffu, sum, off);
    if (lane == 0) sinv[wid] = 1.f / sum;

    // ---- phase 2: cooperative P@V (warp w owns j in [8w, 8w+8) per chunk) ----
    float acc[8][2] = {};
    for (int mc = 0; mc < MEM; mc += 64) {
        __syncthreads();
        for (int i = tid; i < 64 * 16; i += 256) {
            int r = i >> 4, c4 = (i & 15) << 2;
            float4 v = *(const float4*)(Vp + (size_t)(mc + r) * d + base + c4);
            float* dst = ts + r * 65 + c4;
            dst[0] = v.x; dst[1] = v.y; dst[2] = v.z; dst[3] = v.w;
        }
        __syncthreads();
        float v0[8], v1[8];
#pragma unroll
        for (int jl = 0; jl < 8; jl++) {
            v0[jl] = ts[(wid * 8 + jl) * 65 + lane];
            v1[jl] = ts[(wid * 8 + jl) * 65 + lane + 32];
        }
        const int jbase = mc + wid * 8;
#pragma unroll
        for (int q = 0; q < 8; q++) {
            float4 pa4 = *(const float4*)(sc + (q << 11) + jbase);
            float4 pb4 = *(const float4*)(sc + (q << 11) + jbase + 4);
            const float p[8] = {pa4.x, pa4.y, pa4.z, pa4.w, pb4.x, pb4.y, pb4.z, pb4.w};
#pragma unroll
            for (int jl = 0; jl < 8; jl++) {
                acc[q][0] += p[jl] * v0[jl];
                acc[q][1] += p[jl] * v1[jl];
            }
        }
    }

    // ---- cross-warp reduction (reuse ts: 8 warps x 512 floats) ----
    __syncthreads();
#pragma unroll
    for (int q = 0; q < 8; q++) {
        ts[wid * 512 + q * 64 + lane]      = acc[q][0];
        ts[wid * 512 + q * 64 + lane + 32] = acc[q][1];
    }
    __syncthreads();
    for (int oidx = tid; oidx < 512; oidx += 256) {
        const int q = oidx >> 6, c = oidx & 63;
        float s = 0.f;
#pragma unroll
        for (int w = 0; w < 8; w++) s += ts[w * 512 + oidx];
        o[(size_t)(b0 + q) * d + base + c] = s * sinv[q];
    }
}

// ======================= LayerNorm =========================================
__global__ void __launch_bounds__(256) ln_kernel(
    const float* __restrict__ x, const float* __restrict__ g,
    const float* __restrict__ be, float* __restrict__ out)
{
    __shared__ float rs[8], rss[8];
    __shared__ float s_mu, s_inv;
    const int rowi = blockIdx.x;
    const float4* xr = (const float4*)(x + (size_t)rowi * DLLM);
    const int tid = threadIdx.x, lane = tid & 31, warp = tid >> 5;
    float s = 0.f, ss = 0.f;
    for (int i = tid; i < DLLM / 4; i += 256) {
        float4 v = xr[i];
        s  += v.x + v.y + v.z + v.w;
        ss += v.x * v.x + v.y * v.y + v.z * v.z + v.w * v.w;
    }
#pragma unroll
    for (int off = 16; off; off >>= 1) {
        s  += __shfl_xor_sync(0xffffffffu, s, off);
        ss += __shfl_xor_sync(0xffffffffu, ss, off);
    }
    if (lane == 0) { rs[warp] = s; rss[warp] = ss; }
    __syncthreads();
    if (tid == 0) {
        float S = 0.f, SS = 0.f;
#pragma unroll
        for (int w = 0; w < 8; w++) { S += rs[w]; SS += rss[w]; }
        const float mu = S * (1.0f / DLLM);
        const float var = SS * (1.0f / DLLM) - mu * mu;
        s_mu = mu;
        s_inv = rsqrtf(var + 1e-5f);
    }
    __syncthreads();
    const float mu = s_mu, inv = s_inv;
    const float4* g4 = (const float4*)g;
    const float4* b4 = (const float4*)be;
    float4* outr = (float4*)(out + (size_t)rowi * DLLM);
    for (int i = tid; i < DLLM / 4; i += 256) {
        float4 v = xr[i], gv = g4[i], bv = b4[i];
        float4 r;
        r.x = (v.x - mu) * inv * gv.x + bv.x;
        r.y = (v.y - mu) * inv * gv.y + bv.y;
        r.z = (v.z - mu) * inv * gv.z + bv.z;
        r.w = (v.w - mu) * inv * gv.w + bv.w;
        outr[i] = r;
    }
}

// ======================= streams/events (created at init) ==================
struct StreamInit {
    cudaStream_t sA[3], sB[3];
    cudaEvent_t evFork, evKV[3], evD[3];
    StreamInit() {
        for (int i = 0; i < 3; i++) {
            cudaStreamCreateWithFlags(&sA[i], cudaStreamNonBlocking);
            cudaStreamCreateWithFlags(&sB[i], cudaStreamNonBlocking);
            cudaEventCreateWithFlags(&evKV[i], cudaEventDisableTiming);
            cudaEventCreateWithFlags(&evD[i], cudaEventDisableTiming);
        }
        cudaEventCreateWithFlags(&evFork, cudaEventDisableTiming);
    }
};
static StreamInit g_si;

// ======================= host orchestration ================================
extern "C" void kernel_launch(void* const* d_in, const int* in_sizes, int n_in,
                              void* d_out, int out_size)
{
    const float* hidden = (const float*)d_in[0];
    const float* fibers[3] = {(const float*)d_in[1], (const float*)d_in[2], (const float*)d_in[3]};
    const unsigned char* mask = (const unsigned char*)d_in[4];
    const float* Wq[3]    = {(const float*)d_in[5],  (const float*)d_in[7],  (const float*)d_in[9]};
    const float* bq[3]    = {(const float*)d_in[6],  (const float*)d_in[8],  (const float*)d_in[10]};
    const float* Wqkv[3]  = {(const float*)d_in[11], (const float*)d_in[15], (const float*)d_in[19]};
    const float* bqkv[3]  = {(const float*)d_in[12], (const float*)d_in[16], (const float*)d_in[20]};
    const float* Wo[3]    = {(const float*)d_in[13], (const float*)d_in[17], (const float*)d_in[21]};
    const float* bo[3]    = {(const float*)d_in[14], (const float*)d_in[18], (const float*)d_in[22]};
    const float* Wlift[3] = {(const float*)d_in[23], (const float*)d_in[25], (const float*)d_in[27]};
    const float* blift[3] = {(const float*)d_in[24], (const float*)d_in[26], (const float*)d_in[28]};
    const float* lng = (const float*)d_in[29];
    const float* lnb = (const float*)d_in[30];

    const int ds[3]       = {256, 512, 1024};
    const int nhs[3]      = {4, 8, 16};
    const int slots[3]    = {4, 8, 4};
    const int slotBase[3] = {0, 4, 12};
    const size_t kvfOff[3]= {0, 1048576, 3145728};
    const size_t bOff[3]  = {0, 16384, 49152};

    float *prefix, *kvf, *qb, *qp, *oo, *o2;
    cudaGetSymbolAddress((void**)&prefix, g_prefix);
    cudaGetSymbolAddress((void**)&kvf, g_kvf);
    cudaGetSymbolAddress((void**)&qb, g_qb);
    cudaGetSymbolAddress((void**)&qp, g_qp);
    cudaGetSymbolAddress((void**)&oo, g_o);
    cudaGetSymbolAddress((void**)&o2, g_o2);

    cudaFuncSetAttribute(hmma_f32, cudaFuncAttributeMaxDynamicSharedMemorySize, HMMA_SMEM);
    cudaFuncSetAttribute(attn2, cudaFuncAttributeMaxDynamicSharedMemorySize, 21064 * 4);

    // graph root: pre-fill atomic-accumulation targets with biases
    init_bias<<<(114688 + 255) / 256, 256>>>(qb, qp, o2,
        bq[0], bq[1], bq[2], bqkv[0], bqkv[1], bqkv[2], bo[0], bo[1], bo[2]);
    cudaEventRecord(g_si.evFork, 0);

    for (int b = 0; b < 3; b++) {
        const int d = ds[b], nh = nhs[b], s = slots[b];
        cudaStream_t A = g_si.sA[b], Bs = g_si.sB[b];

        // ---- stream A: KV projection ----
        cudaStreamWaitEvent(A, g_si.evFork, 0);
        hmma_f32<<<dim3(d / 64, MEM / 128, 2), 256, HMMA_SMEM, A>>>(
            fibers[b], Wqkv[b] + (size_t)d * d, bqkv[b] + d, d,
            kvf + kvfOff[b], d, (long long)MEM * d,
            (long long)d * d, d, d, MEM, MEM, 0, 0, 1.0f);
        cudaEventRecord(g_si.evKV[b], A);

        // ---- stream B: q chain -> attention -> out-proj -> lift ----
        cudaStreamWaitEvent(Bs, g_si.evFork, 0);
        // q-head: K=4096 split 16x256, atomic into pre-biased qb
        hmma_f32<<<dim3(d / 64, 1, 16), 256, HMMA_SMEM, Bs>>>(
            hidden, Wq[b], nullptr, 0,
            qb + bOff[b], d, 0,
            0, DLLM, DLLM, BATCH, BATCH, 256, 0, 1.0f);
        // q in-proj: K=d split 4, atomic alpha=0.125 into pre-biased qp
        hmma_f32<<<dim3(d / 64, 1, 4), 256, HMMA_SMEM, Bs>>>(
            qb + bOff[b], Wqkv[b], nullptr, 0,
            qp + bOff[b], d, 0,
            0, d, d, BATCH, BATCH, d / 4, 0, 0.125f);
        cudaStreamWaitEvent(Bs, g_si.evKV[b], 0);
        attn2<<<dim3(nh, BATCH / 8), 256, 21064 * 4, Bs>>>(
            qp + bOff[b], kvf + kvfOff[b], kvf + kvfOff[b] + (size_t)MEM * d, mask, oo + bOff[b], d);
        // out-proj: K=d split 4, atomic into pre-biased o2
        hmma_f32<<<dim3(d / 64, 1, 4), 256, HMMA_SMEM, Bs>>>(
            oo + bOff[b], Wo[b], nullptr, 0,
            o2 + bOff[b], d, 0,
            0, d, d, BATCH, BATCH, d / 4, 0, 1.0f);
        // lift
        hmma_f32<<<dim3(DLLM / 64, 1, s), 256, HMMA_SMEM, Bs>>>(
            o2 + bOff[b], Wlift[b], blift[b], DLLM,
            prefix + (size_t)slotBase[b] * DLLM, 16 * DLLM, DLLM,
            (long long)d * DLLM, d, DLLM, BATCH, BATCH, 0, 1, 1.0f);
        cudaEventRecord(g_si.evD[b], Bs);
    }

    for (int b = 0; b < 3; b++) cudaStreamWaitEvent(0, g_si.evD[b], 0);
    ln_kernel<<<BATCH * 16, 256>>>(prefix, lng, lnb, (float*)d_out);
}

// round 11
// speedup vs baseline: 2.4725x; 1.0780x over previous
#include <cuda_runtime.h>
#include <cuda_bf16.h>
#include <cstdint>

// ---------------------------------------------------------------------------
// CrossBundleAttention — HMMA hi/lo GEMMs + split-KV attention + per-bundle LN
// B=64, M=2048, D_LLM=4096, bundles: (d=256,nh=4,s=4) (512,8,8) (1024,16,4)
// ---------------------------------------------------------------------------

#define BATCH 64
#define MEM   2048
#define DLLM  4096
#define STR   72

// ======================= scratch (device globals) ==========================
__device__ float g_prefix[4194304];
__device__ float g_kvf[7340032];
__device__ float g_qb[114688], g_qp[114688], g_o[114688], g_o2[114688];
__device__ float g_u[393216];        // attention split partials (unnormalized)
__device__ float g_ms[24576];        // (m, s) per (b, h, split)

// ======================= HMMA helpers ======================================
__device__ __forceinline__ void mma16816(float* c, const uint32_t* a, const uint32_t* b) {
    asm volatile(
        "mma.sync.aligned.m16n8k16.row.col.f32.bf16.bf16.f32 "
        "{%0,%1,%2,%3}, {%4,%5,%6,%7}, {%8,%9}, {%0,%1,%2,%3};"
        : "+f"(c[0]), "+f"(c[1]), "+f"(c[2]), "+f"(c[3])
        : "r"(a[0]), "r"(a[1]), "r"(a[2]), "r"(a[3]), "r"(b[0]), "r"(b[1]));
}
__device__ __forceinline__ void ldm4(uint32_t* r, const __nv_bfloat16* p) {
    uint32_t a = (uint32_t)__cvta_generic_to_shared(p);
    asm volatile("ldmatrix.sync.aligned.m8n8.x4.shared.b16 {%0,%1,%2,%3}, [%4];"
        : "=r"(r[0]), "=r"(r[1]), "=r"(r[2]), "=r"(r[3]) : "r"(a));
}
__device__ __forceinline__ uint32_t pack2(__nv_bfloat16 a, __nv_bfloat16 b) {
    __nv_bfloat162 p(a, b);
    return *(uint32_t*)&p;
}
__device__ __forceinline__ void cvt4(float4 v, uint2& hh, uint2& ll) {
    __nv_bfloat16 h0 = __float2bfloat16(v.x), h1 = __float2bfloat16(v.y);
    __nv_bfloat16 h2 = __float2bfloat16(v.z), h3 = __float2bfloat16(v.w);
    __nv_bfloat16 l0 = __float2bfloat16(v.x - __bfloat162float(h0));
    __nv_bfloat16 l1 = __float2bfloat16(v.y - __bfloat162float(h1));
    __nv_bfloat16 l2 = __float2bfloat16(v.z - __bfloat162float(h2));
    __nv_bfloat16 l3 = __float2bfloat16(v.w - __bfloat162float(h3));
    hh.x = pack2(h0, h1); hh.y = pack2(h2, h3);
    ll.x = pack2(l0, l1); ll.y = pack2(l2, l3);
}

#define HMMA_SMEM ((2 * 128 * STR + 2 * 64 * STR) * 2)   // 55296 B

// ---------------------------------------------------------------------------
// Fused-conversion hi/lo HMMA GEMM (unchanged from R10).
// ---------------------------------------------------------------------------
__global__ void __launch_bounds__(256) hmma_f32(
    const float* __restrict__ A, const float* __restrict__ Bm,
    const float* __restrict__ bias, long long bias_zstr,
    float* __restrict__ C, long long c_row, long long c_zstr,
    long long b_zstr, int K, int ldb, int a_rows, int m_valid,
    int kslice, int transB, float alpha)
{
    extern __shared__ __nv_bfloat16 sm[];
    __nv_bfloat16* Ah = sm;
    __nv_bfloat16* Al = sm + 128 * STR;
    __nv_bfloat16* Bh = sm + 2 * 128 * STR;
    __nv_bfloat16* Bl = Bh + 64 * STR;

    const int tid = threadIdx.x, wid = tid >> 5, lane = tid & 31;
    const int nBase = blockIdx.x << 6, mBase = blockIdx.y << 7, z = blockIdx.z;

    int k0s, k0e;
    const float* bp;
    if (kslice) {
        k0s = z * kslice; k0e = k0s + kslice;
        bp = Bm;
    } else {
        k0s = 0; k0e = K;
        bp = Bm + (size_t)z * b_zstr;
    }

    const int mW = (wid >> 1) << 5;
    const int nW = (wid & 1) << 5;
    const int grp = lane >> 2, qid = lane & 3;
    const int lane7 = lane & 7, l8 = (lane >> 3) & 1, l16 = (lane >> 4) & 1;
    const int aOff = (lane7 + l8 * 8) * STR + l16 * 8;
    const int bOff = (lane7 + l16 * 8) * STR + l8 * 8;

    const int ar = tid >> 4, ac4 = (tid & 15) << 2;
    float acc[2][4][4] = {};
    float4 pa[8], pb[4];

    auto loadA = [&](int k0) {
#pragma unroll
        for (int it = 0; it < 8; it++) {
            const int r = ar + it * 16;
            if (mBase + r < a_rows)
                pa[it] = *(const float4*)(A + (size_t)(mBase + r) * K + k0 + ac4);
            else
                pa[it] = make_float4(0.f, 0.f, 0.f, 0.f);
        }
    };
    auto loadB = [&](int k0) {
        if (!transB) {
#pragma unroll
            for (int it = 0; it < 4; it++) {
                const int r = ar + it * 16;
                pb[it] = *(const float4*)(bp + (size_t)(nBase + r) * K + k0 + ac4);
            }
        } else {
#pragma unroll
            for (int it = 0; it < 4; it++) {
                const int kr = ar + it * 16;
                pb[it] = *(const float4*)(bp + (size_t)(k0 + kr) * ldb + nBase + ac4);
            }
        }
    };
    auto storeAB = [&]() {
#pragma unroll
        for (int it = 0; it < 8; it++) {
            const int r = ar + it * 16;
            uint2 hh, ll;
            cvt4(pa[it], hh, ll);
            *(uint2*)(Ah + r * STR + ac4) = hh;
            *(uint2*)(Al + r * STR + ac4) = ll;
        }
        if (!transB) {
#pragma unroll
            for (int it = 0; it < 4; it++) {
                const int r = ar + it * 16;
                uint2 hh, ll;
                cvt4(pb[it], hh, ll);
                *(uint2*)(Bh + r * STR + ac4) = hh;
                *(uint2*)(Bl + r * STR + ac4) = ll;
            }
        } else {
#pragma unroll
            for (int it = 0; it < 4; it++) {
                const int kr = ar + it * 16;
                const float vv[4] = {pb[it].x, pb[it].y, pb[it].z, pb[it].w};
#pragma unroll
                for (int j = 0; j < 4; j++) {
                    __nv_bfloat16 h = __float2bfloat16(vv[j]);
                    Bh[(ac4 + j) * STR + kr] = h;
                    Bl[(ac4 + j) * STR + kr] = __float2bfloat16(vv[j] - __bfloat162float(h));
                }
            }
        }
    };

    loadA(k0s);
    loadB(k0s);

    for (int k0 = k0s; k0 < k0e; k0 += 64) {
        __syncthreads();
        storeAB();
        __syncthreads();
        if (k0 + 64 < k0e) {
            loadA(k0 + 64);
            loadB(k0 + 64);
        }

#pragma unroll
        for (int kk = 0; kk < 4; kk++) {
            const int kc = kk << 4;
            uint32_t ah[2][4], al[2][4], bhf[4][2], blf[4][2], t4[4];
#pragma unroll
            for (int mi = 0; mi < 2; mi++) {
                ldm4(ah[mi], Ah + (mW + mi * 16) * STR + kc + aOff);
                ldm4(al[mi], Al + (mW + mi * 16) * STR + kc + aOff);
            }
#pragma unroll
            for (int p = 0; p < 2; p++) {
                ldm4(t4, Bh + (nW + p * 16) * STR + kc + bOff);
                bhf[p * 2][0] = t4[0]; bhf[p * 2][1] = t4[1];
                bhf[p * 2 + 1][0] = t4[2]; bhf[p * 2 + 1][1] = t4[3];
                ldm4(t4, Bl + (nW + p * 16) * STR + kc + bOff);
                blf[p * 2][0] = t4[0]; blf[p * 2][1] = t4[1];
                blf[p * 2 + 1][0] = t4[2]; blf[p * 2 + 1][1] = t4[3];
            }
#pragma unroll
            for (int mi = 0; mi < 2; mi++)
#pragma unroll
                for (int ni = 0; ni < 4; ni++) {
                    mma16816(acc[mi][ni], ah[mi], bhf[ni]);
                    mma16816(acc[mi][ni], ah[mi], blf[ni]);
                    mma16816(acc[mi][ni], al[mi], bhf[ni]);
                }
        }
    }

    if (kslice) {
#pragma unroll
        for (int mi = 0; mi < 2; mi++) {
            const int r0 = mBase + mW + mi * 16 + grp;
#pragma unroll
            for (int ni = 0; ni < 4; ni++) {
                const int c = nBase + nW + ni * 8 + qid * 2;
                if (r0 < m_valid) {
                    atomicAdd(C + (size_t)r0 * c_row + c,     alpha * acc[mi][ni][0]);
                    atomicAdd(C + (size_t)r0 * c_row + c + 1, alpha * acc[mi][ni][1]);
                }
                if (r0 + 8 < m_valid) {
                    atomicAdd(C + (size_t)(r0 + 8) * c_row + c,     alpha * acc[mi][ni][2]);
                    atomicAdd(C + (size_t)(r0 + 8) * c_row + c + 1, alpha * acc[mi][ni][3]);
                }
            }
        }
    } else {
        float* Cz = C + (size_t)z * c_zstr;
        const float* brow = bias + (size_t)z * bias_zstr;
#pragma unroll
        for (int mi = 0; mi < 2; mi++) {
            const int r0 = mBase + mW + mi * 16 + grp;
#pragma unroll
            for (int ni = 0; ni < 4; ni++) {
                const int c = nBase + nW + ni * 8 + qid * 2;
                const float b0 = brow[c], b1 = brow[c + 1];
                if (r0 < m_valid) {
                    float2 v = {acc[mi][ni][0] + b0, acc[mi][ni][1] + b1};
                    *(float2*)(Cz + (size_t)r0 * c_row + c) = v;
                }
                if (r0 + 8 < m_valid) {
                    float2 v = {acc[mi][ni][2] + b0, acc[mi][ni][3] + b1};
                    *(float2*)(Cz + (size_t)(r0 + 8) * c_row + c) = v;
                }
            }
        }
    }
}

// =============== graph root: fill qb/qp/o2 with (scaled) biases =============
__global__ void init_bias(float* __restrict__ qb, float* __restrict__ qp,
                          float* __restrict__ o2,
                          const float* bq0, const float* bq1, const float* bq2,
                          const float* bi0, const float* bi1, const float* bi2,
                          const float* bo0, const float* bo1, const float* bo2)
{
    const int i = blockIdx.x * 256 + threadIdx.x;
    if (i >= 114688) return;
    int n;
    const float *bqv, *biv, *bov;
    if (i < 16384)       { n = i & 255;             bqv = bq0; biv = bi0; bov = bo0; }
    else if (i < 49152)  { n = (i - 16384) & 511;   bqv = bq1; biv = bi1; bov = bo1; }
    else                 { n = (i - 49152) & 1023;  bqv = bq2; biv = bi2; bov = bo2; }
    qb[i] = bqv[n];
    qp[i] = 0.125f * biv[n];
    o2[i] = bov[n];
}

// ======================= split-KV batched attention ========================
// grid (nh, B/8, splits); block 256. Split z covers m in [z*mlen, z*mlen+mlen).
// Outputs unnormalized u[(b*nh+h)*splits+z][64] and (m, s) per (b,h,z).
// smem floats: qs[512] | sc[8*mlen] | ts[4160]
__global__ void __launch_bounds__(256) attn_split(
    const float* __restrict__ qp, const float* __restrict__ Kp,
    const float* __restrict__ Vp, const unsigned char* __restrict__ mask,
    float* __restrict__ u, float* __restrict__ ms,
    int d, int mlen, int splits)
{
    extern __shared__ float smf[];
    float* qs = smf;
    float* sc = smf + 512;
    float* ts = smf + 512 + 8 * mlen;

    const int nh = gridDim.x;
    const int h = blockIdx.x, b0 = blockIdx.y << 3, z = blockIdx.z;
    const int base = h << 6;
    const int m0 = z * mlen;
    const int tid = threadIdx.x, lane = tid & 31, wid = tid >> 5;

    for (int i = tid; i < 512; i += 256) {
        int qq = i >> 6, k = i & 63;
        qs[i] = qp[(size_t)(b0 + qq) * d + base + k];
    }
    __syncthreads();

    const float4* qs4 = (const float4*)(qs + (wid << 6));
    const unsigned char* mrow = mask + (size_t)(b0 + wid) * MEM + m0;

    // ---- phase 1: scores (warp = query) ----
    for (int mc = 0; mc < mlen; mc += 64) {
        for (int i = tid; i < 64 * 16; i += 256) {
            int r = i >> 4, c4 = (i & 15) << 2;
            float4 v = *(const float4*)(Kp + (size_t)(m0 + mc + r) * d + base + c4);
            float* dst = ts + r * 65 + c4;
            dst[0] = v.x; dst[1] = v.y; dst[2] = v.z; dst[3] = v.w;
        }
        __syncthreads();
        float acc0 = 0.f, acc1 = 0.f;
        const float* t0 = ts + lane * 65;
        const float* t1 = ts + (lane + 32) * 65;
#pragma unroll
        for (int k4 = 0; k4 < 16; k4++) {
            float4 qv = qs4[k4];
            acc0 += qv.x * t0[k4 * 4] + qv.y * t0[k4 * 4 + 1] + qv.z * t0[k4 * 4 + 2] + qv.w * t0[k4 * 4 + 3];
            acc1 += qv.x * t1[k4 * 4] + qv.y * t1[k4 * 4 + 1] + qv.z * t1[k4 * 4 + 2] + qv.w * t1[k4 * 4 + 3];
        }
        sc[wid * mlen + mc + lane]      = mrow[mc + lane]      ? -1e9f : acc0;
        sc[wid * mlen + mc + 32 + lane] = mrow[mc + 32 + lane] ? -1e9f : acc1;
        __syncthreads();
    }

    // ---- local softmax over split (warp = query) ----
    float* row = sc + wid * mlen;
    float mx = -1e30f;
    for (int i = lane; i < mlen; i += 32) mx = fmaxf(mx, row[i]);
#pragma unroll
    for (int off = 16; off; off >>= 1) mx = fmaxf(mx, __shfl_xor_sync(0xffffffffu, mx, off));
    float sum = 0.f;
    for (int i = lane; i < mlen; i += 32) {
        float e = __expf(row[i] - mx);
        row[i] = e;
        sum += e;
    }
#pragma unroll
    for (int off = 16; off; off >>= 1) sum += __shfl_xor_sync(0xffffffffu, sum, off);
    if (lane == 0) {
        const int idx = ((b0 + wid) * nh + h) * splits + z;
        ms[idx * 2]     = mx;
        ms[idx * 2 + 1] = sum;
    }

    // ---- phase 2: cooperative P@V (warp w owns j in [8w, 8w+8) per chunk) ----
    float acc[8][2] = {};
    for (int mc = 0; mc < mlen; mc += 64) {
        __syncthreads();
        for (int i = tid; i < 64 * 16; i += 256) {
            int r = i >> 4, c4 = (i & 15) << 2;
            float4 v = *(const float4*)(Vp + (size_t)(m0 + mc + r) * d + base + c4);
            float* dst = ts + r * 65 + c4;
            dst[0] = v.x; dst[1] = v.y; dst[2] = v.z; dst[3] = v.w;
        }
        __syncthreads();
        float v0[8], v1[8];
#pragma unroll
        for (int jl = 0; jl < 8; jl++) {
            v0[jl] = ts[(wid * 8 + jl) * 65 + lane];
            v1[jl] = ts[(wid * 8 + jl) * 65 + lane + 32];
        }
        const int jbase = mc + wid * 8;
#pragma unroll
        for (int q = 0; q < 8; q++) {
            float4 pa4 = *(const float4*)(sc + q * mlen + jbase);
            float4 pb4 = *(const float4*)(sc + q * mlen + jbase + 4);
            const float p[8] = {pa4.x, pa4.y, pa4.z, pa4.w, pb4.x, pb4.y, pb4.z, pb4.w};
#pragma unroll
            for (int jl = 0; jl < 8; jl++) {
                acc[q][0] += p[jl] * v0[jl];
                acc[q][1] += p[jl] * v1[jl];
            }
        }
    }

    // ---- cross-warp reduction (ts: 8 warps x 512 floats) ----
    __syncthreads();
#pragma unroll
    for (int q = 0; q < 8; q++) {
        ts[wid * 512 + q * 64 + lane]      = acc[q][0];
        ts[wid * 512 + q * 64 + lane + 32] = acc[q][1];
    }
    __syncthreads();
    for (int oidx = tid; oidx < 512; oidx += 256) {
        const int q = oidx >> 6, c = oidx & 63;
        float s = 0.f;
#pragma unroll
        for (int w = 0; w < 8; w++) s += ts[w * 512 + oidx];
        u[((size_t)((b0 + q) * nh + h) * splits + z) * 64 + c] = s;
    }
}

// combine split partials: O = sum_z e^{m_z-M} u_z / sum_z e^{m_z-M} s_z
__global__ void attn_combine(const float* __restrict__ u, const float* __restrict__ ms,
                             float* __restrict__ o, int d, int nh, int splits)
{
    const int bh = blockIdx.x;           // b*nh + h
    const int b = bh / nh, h = bh % nh, c = threadIdx.x;
    float M = -1e30f;
    for (int z = 0; z < splits; z++) M = fmaxf(M, ms[(bh * splits + z) * 2]);
    float S = 0.f, O = 0.f;
    for (int z = 0; z < splits; z++) {
        const float w = __expf(ms[(bh * splits + z) * 2] - M);
        S += w * ms[(bh * splits + z) * 2 + 1];
        O += w * u[((size_t)bh * splits + z) * 64 + c];
    }
    o[(size_t)b * d + (h << 6) + c] = O / S;
}

// ======================= per-bundle LayerNorm ==============================
__global__ void __launch_bounds__(256) ln_kernel(
    const float* __restrict__ x, const float* __restrict__ g,
    const float* __restrict__ be, float* __restrict__ out,
    int slotBase, int nslots)
{
    __shared__ float rs[8], rss[8];
    __shared__ float s_mu, s_inv;
    const int bi = blockIdx.x / nslots, slot = slotBase + blockIdx.x % nslots;
    const int rowi = bi * 16 + slot;
    const float4* xr = (const float4*)(x + (size_t)rowi * DLLM);
    const int tid = threadIdx.x, lane = tid & 31, warp = tid >> 5;
    float s = 0.f, ss = 0.f;
    for (int i = tid; i < DLLM / 4; i += 256) {
        float4 v = xr[i];
        s  += v.x + v.y + v.z + v.w;
        ss += v.x * v.x + v.y * v.y + v.z * v.z + v.w * v.w;
    }
#pragma unroll
    for (int off = 16; off; off >>= 1) {
        s  += __shfl_xor_sync(0xffffffffu, s, off);
        ss += __shfl_xor_sync(0xffffffffu, ss, off);
    }
    if (lane == 0) { rs[warp] = s; rss[warp] = ss; }
    __syncthreads();
    if (tid == 0) {
        float S = 0.f, SS = 0.f;
#pragma unroll
        for (int w = 0; w < 8; w++) { S += rs[w]; SS += rss[w]; }
        const float mu = S * (1.0f / DLLM);
        const float var = SS * (1.0f / DLLM) - mu * mu;
        s_mu = mu;
        s_inv = rsqrtf(var + 1e-5f);
    }
    __syncthreads();
    const float mu = s_mu, inv = s_inv;
    const float4* g4 = (const float4*)g;
    const float4* b4 = (const float4*)be;
    float4* outr = (float4*)(out + (size_t)rowi * DLLM);
    for (int i = tid; i < DLLM / 4; i += 256) {
        float4 v = xr[i], gv = g4[i], bv = b4[i];
        float4 r;
        r.x = (v.x - mu) * inv * gv.x + bv.x;
        r.y = (v.y - mu) * inv * gv.y + bv.y;
        r.z = (v.z - mu) * inv * gv.z + bv.z;
        r.w = (v.w - mu) * inv * gv.w + bv.w;
        outr[i] = r;
    }
}

// ======================= streams/events (created at init) ==================
struct StreamInit {
    cudaStream_t sA[3], sB[3];
    cudaEvent_t evFork, evKV[3], evD[3];
    StreamInit() {
        for (int i = 0; i < 3; i++) {
            cudaStreamCreateWithFlags(&sA[i], cudaStreamNonBlocking);
            cudaStreamCreateWithFlags(&sB[i], cudaStreamNonBlocking);
            cudaEventCreateWithFlags(&evKV[i], cudaEventDisableTiming);
            cudaEventCreateWithFlags(&evD[i], cudaEventDisableTiming);
        }
        cudaEventCreateWithFlags(&evFork, cudaEventDisableTiming);
    }
};
static StreamInit g_si;

// ======================= host orchestration ================================
extern "C" void kernel_launch(void* const* d_in, const int* in_sizes, int n_in,
                              void* d_out, int out_size)
{
    const float* hidden = (const float*)d_in[0];
    const float* fibers[3] = {(const float*)d_in[1], (const float*)d_in[2], (const float*)d_in[3]};
    const unsigned char* mask = (const unsigned char*)d_in[4];
    const float* Wq[3]    = {(const float*)d_in[5],  (const float*)d_in[7],  (const float*)d_in[9]};
    const float* bq[3]    = {(const float*)d_in[6],  (const float*)d_in[8],  (const float*)d_in[10]};
    const float* Wqkv[3]  = {(const float*)d_in[11], (const float*)d_in[15], (const float*)d_in[19]};
    const float* bqkv[3]  = {(const float*)d_in[12], (const float*)d_in[16], (const float*)d_in[20]};
    const float* Wo[3]    = {(const float*)d_in[13], (const float*)d_in[17], (const float*)d_in[21]};
    const float* bo[3]    = {(const float*)d_in[14], (const float*)d_in[18], (const float*)d_in[22]};
    const float* Wlift[3] = {(const float*)d_in[23], (const float*)d_in[25], (const float*)d_in[27]};
    const float* blift[3] = {(const float*)d_in[24], (const float*)d_in[26], (const float*)d_in[28]};
    const float* lng = (const float*)d_in[29];
    const float* lnb = (const float*)d_in[30];

    const int ds[3]       = {256, 512, 1024};
    const int nhs[3]      = {4, 8, 16};
    const int slots[3]    = {4, 8, 4};
    const int slotBase[3] = {0, 4, 12};
    const int splits[3]   = {8, 4, 2};
    const size_t kvfOff[3]= {0, 1048576, 3145728};
    const size_t bOff[3]  = {0, 16384, 49152};
    const size_t uOff[3]  = {0, 131072, 262144};
    const size_t msOff[3] = {0, 4096, 8192};

    float *prefix, *kvf, *qb, *qp, *oo, *o2, *uu, *msb;
    cudaGetSymbolAddress((void**)&prefix, g_prefix);
    cudaGetSymbolAddress((void**)&kvf, g_kvf);
    cudaGetSymbolAddress((void**)&qb, g_qb);
    cudaGetSymbolAddress((void**)&qp, g_qp);
    cudaGetSymbolAddress((void**)&oo, g_o);
    cudaGetSymbolAddress((void**)&o2, g_o2);
    cudaGetSymbolAddress((void**)&uu, g_u);
    cudaGetSymbolAddress((void**)&msb, g_ms);

    cudaFuncSetAttribute(hmma_f32, cudaFuncAttributeMaxDynamicSharedMemorySize, HMMA_SMEM);
    cudaFuncSetAttribute(attn_split, cudaFuncAttributeMaxDynamicSharedMemorySize,
                         (512 + 8 * 1024 + 4160) * 4);

    init_bias<<<(114688 + 255) / 256, 256>>>(qb, qp, o2,
        bq[0], bq[1], bq[2], bqkv[0], bqkv[1], bqkv[2], bo[0], bo[1], bo[2]);
    cudaEventRecord(g_si.evFork, 0);

    for (int b = 0; b < 3; b++) {
        const int d = ds[b], nh = nhs[b], s = slots[b], sp = splits[b];
        const int mlen = MEM / sp;
        const int attn_smem = (512 + 8 * mlen + 4160) * 4;
        cudaStream_t A = g_si.sA[b], Bs = g_si.sB[b];

        // ---- stream A: KV projection ----
        cudaStreamWaitEvent(A, g_si.evFork, 0);
        hmma_f32<<<dim3(d / 64, MEM / 128, 2), 256, HMMA_SMEM, A>>>(
            fibers[b], Wqkv[b] + (size_t)d * d, bqkv[b] + d, d,
            kvf + kvfOff[b], d, (long long)MEM * d,
            (long long)d * d, d, d, MEM, MEM, 0, 0, 1.0f);
        cudaEventRecord(g_si.evKV[b], A);

        // ---- stream B: q chain -> attention -> out-proj -> lift -> LN ----
        cudaStreamWaitEvent(Bs, g_si.evFork, 0);
        hmma_f32<<<dim3(d / 64, 1, 16), 256, HMMA_SMEM, Bs>>>(
            hidden, Wq[b], nullptr, 0,
            qb + bOff[b], d, 0,
            0, DLLM, DLLM, BATCH, BATCH, 256, 0, 1.0f);
        hmma_f32<<<dim3(d / 64, 1, 4), 256, HMMA_SMEM, Bs>>>(
            qb + bOff[b], Wqkv[b], nullptr, 0,
            qp + bOff[b], d, 0,
            0, d, d, BATCH, BATCH, d / 4, 0, 0.125f);
        cudaStreamWaitEvent(Bs, g_si.evKV[b], 0);
        attn_split<<<dim3(nh, BATCH / 8, sp), 256, attn_smem, Bs>>>(
            qp + bOff[b], kvf + kvfOff[b], kvf + kvfOff[b] + (size_t)MEM * d, mask,
            uu + uOff[b], msb + msOff[b], d, mlen, sp);
        attn_combine<<<BATCH * nh, 64, 0, Bs>>>(
            uu + uOff[b], msb + msOff[b], oo + bOff[b], d, nh, sp);
        hmma_f32<<<dim3(d / 64, 1, 4), 256, HMMA_SMEM, Bs>>>(
            oo + bOff[b], Wo[b], nullptr, 0,
            o2 + bOff[b], d, 0,
            0, d, d, BATCH, BATCH, d / 4, 0, 1.0f);
        hmma_f32<<<dim3(DLLM / 64, 1, s), 256, HMMA_SMEM, Bs>>>(
            o2 + bOff[b], Wlift[b], blift[b], DLLM,
            prefix + (size_t)slotBase[b] * DLLM, 16 * DLLM, DLLM,
            (long long)d * DLLM, d, DLLM, BATCH, BATCH, 0, 1, 1.0f);
        ln_kernel<<<BATCH * s, 256, 0, Bs>>>(
            prefix, lng, lnb, (float*)d_out, slotBase[b], s);
        cudaEventRecord(g_si.evD[b], Bs);
    }

    for (int b = 0; b < 3; b++) cudaStreamWaitEvent(0, g_si.evD[b], 0);
}